// round 9
// baseline (speedup 1.0000x reference)
#include <cuda_runtime.h>
#include <math.h>

__device__ float g_h1a[(size_t)512 * 32 * 144];
__device__ float g_h1b[(size_t)512 * 32 * 144];
__device__ float g_h4[(size_t)512 * 64 * 144];
__device__ float g_xz[(size_t)512 * 64 * 576];

__device__ __forceinline__ float d4(float4 a, float4 b) {
    return a.x * b.x + a.y * b.y + a.z * b.z + a.w * b.w;
}

// ============ kernel 1: conv1 partial (100 ics per CTA), raw sums ============
// grid = B (2 images x 2 ic-halves per pair); 288 threads; thread = img x 2row x 4col x 4oc
__global__ void __launch_bounds__(288, 3) k_front(
    const float* __restrict__ x, const float* __restrict__ w1)
{
    __shared__ float xs[2][1960];        // 2 img x 10 ic x 14x14 padded
    __shared__ float ws[2880];           // 10 ic x 9 tap x 32 oc
    int tid = threadIdx.x;
    int bid = blockIdx.x;
    size_t bi2 = (size_t)(bid >> 1) * 2;
    int half = bid & 1;
    int img = tid / 144, r = tid - img * 144;
    int pg = r % 18, ocg = r / 18;       // 18 pos-tiles, 8 oc-groups(4oc)
    int ry = (pg / 3) * 2, cx = (pg % 3) * 4;
    float acc[2][4][4] = {};
    for (int i = tid; i < 3920; i += 288) ((float*)xs)[i] = 0.f;

    for (int ch = 0; ch < 10; ch++) {
        int c0 = half * 100 + ch * 10;
        __syncthreads();
        for (int i = tid; i < 2880; i += 288) {
            int im = i / 1440, j = i - im * 1440;
            int ic = j / 144, pos = j - ic * 144;
            int y = pos / 12, xx = pos - y * 12;
            xs[im][ic * 196 + (y + 1) * 14 + xx + 1] =
                x[(bi2 + im) * 28800 + (c0 + ic) * 144 + pos];
        }
        for (int i = tid; i < 2880; i += 288) {
            int ic = i / 288, rr = i - ic * 288;
            ws[i] = w1[(rr & 31) * 1800 + (c0 + ic) * 9 + (rr >> 5)];
        }
        __syncthreads();
#pragma unroll 1
        for (int ic = 0; ic < 10; ic++) {
            float xv[4][6];
            const float* xp = &xs[img][ic * 196 + ry * 14 + cx];
#pragma unroll
            for (int rr = 0; rr < 4; rr++)
#pragma unroll
                for (int cc = 0; cc < 6; cc++) xv[rr][cc] = xp[rr * 14 + cc];
#pragma unroll
            for (int k = 0; k < 9; k++) {
                float4 wv = *(const float4*)&ws[ic * 288 + k * 32 + ocg * 4];
                int kr = k / 3, kc = k % 3;
#pragma unroll
                for (int orow = 0; orow < 2; orow++)
#pragma unroll
                    for (int q = 0; q < 4; q++) {
                        float xvv = xv[orow + kr][kc + q];
                        acc[orow][0][q] += wv.x * xvv;
                        acc[orow][1][q] += wv.y * xvv;
                        acc[orow][2][q] += wv.z * xvv;
                        acc[orow][3][q] += wv.w * xvv;
                    }
            }
        }
    }
    float* obuf = half ? g_h1b : g_h1a;
#pragma unroll
    for (int o = 0; o < 4; o++) {
        int oc = ocg * 4 + o;
#pragma unroll
        for (int orow = 0; orow < 2; orow++) {
            float4 v = {acc[orow][o][0], acc[orow][o][1], acc[orow][o][2], acc[orow][o][3]};
            *(float4*)&obuf[(bi2 + img) * 4608 + oc * 144 + (ry + orow) * 12 + cx] = v;
        }
    }
}

// ============ kernel 2: (merge+BN1+ReLU) -> conv2+BN+ReLU -> we -> wc2 -> in_w ============
// arena 18944 fl (75776 B), 3 CTAs/SM:
//   phase A: img[0,6272), bn[6272,6336), ws2[6336,10944); h2 written to [0,9472) after
//   phase B+: h2/h4 [0,9472) stride148, h3 [9472,18944) stride148
//   weights for B/C/D streamed from L2 (__ldg), no staging
__global__ void __launch_bounds__(288, 3) k_mid(
    const float* __restrict__ g1, const float* __restrict__ be1,
    const float* __restrict__ m1, const float* __restrict__ v1,
    const float* __restrict__ b1,
    const float* __restrict__ w2, const float* __restrict__ b2,
    const float* __restrict__ g2, const float* __restrict__ be2,
    const float* __restrict__ m2, const float* __restrict__ v2,
    const float* __restrict__ wc2, const float* __restrict__ bc2,
    const float* __restrict__ we, const float* __restrict__ bee,
    const float* __restrict__ in_w)
{
    extern __shared__ float sm[];
    float* img = sm;                 // 6272
    float* bninv = sm + 6272;        // 32
    float* bnsh = sm + 6304;         // 32
    float* ws2 = sm + 6336;          // 4608
    float* h2 = sm;                  // 9472 (after phase A)
    float* h4 = sm;
    float* h3 = sm + 9472;           // 9472
    int bi = blockIdx.x, tid = threadIdx.x;

    // ---- BN1 consts + zero img borders ----
    if (tid < 32) {
        float inv = g1[tid] * rsqrtf(v1[tid] + 1e-5f);
        bninv[tid] = inv;
        bnsh[tid] = (b1[tid] - m1[tid]) * inv + be1[tid];
    }
    for (int i = tid; i < 6272; i += 288) img[i] = 0.f;
    __syncthreads();
    // ---- merge halves + BN1 + ReLU into padded img ----
    {
        const float* pa = g_h1a + (size_t)bi * 4608;
        const float* pb = g_h1b + (size_t)bi * 4608;
        for (int i = tid; i < 4608; i += 288) {
            int ic = i / 144, pos = i - ic * 144;
            int y = pos / 12, xx = pos - y * 12;
            float v = (pa[i] + pb[i]) * bninv[ic] + bnsh[ic];
            img[ic * 196 + (y + 1) * 14 + xx + 1] = fmaxf(v, 0.f);
        }
    }

    // ---- phase A: conv2(32->64)+BN+ReLU, 288 threads: 18 pos x 16 ocg x 4oc ----
    {
        int pg = tid % 18, ocg = tid / 18;       // ocg 0..15
        int ry = (pg / 3) * 2, cx = (pg % 3) * 4;
        float acc[2][4][4] = {};
        for (int c0 = 0; c0 < 32; c0 += 8) {
            __syncthreads();
            for (int i = tid; i < 4608; i += 288) {
                int ic = i / 576, rr = i - ic * 576;
                ws2[i] = w2[(rr & 63) * 288 + (c0 + ic) * 9 + (rr >> 6)];
            }
            __syncthreads();
#pragma unroll 1
            for (int ic = 0; ic < 8; ic++) {
                float xv[4][6];
                const float* xp = &img[(c0 + ic) * 196 + ry * 14 + cx];
#pragma unroll
                for (int rr = 0; rr < 4; rr++)
#pragma unroll
                    for (int cc = 0; cc < 6; cc++) xv[rr][cc] = xp[rr * 14 + cc];
#pragma unroll
                for (int k = 0; k < 9; k++) {
                    float4 wv = *(const float4*)&ws2[ic * 576 + k * 64 + ocg * 4];
                    int kr = k / 3, kc = k % 3;
#pragma unroll
                    for (int orow = 0; orow < 2; orow++)
#pragma unroll
                        for (int q = 0; q < 4; q++) {
                            float xvv = xv[orow + kr][kc + q];
                            acc[orow][0][q] += wv.x * xvv;
                            acc[orow][1][q] += wv.y * xvv;
                            acc[orow][2][q] += wv.z * xvv;
                            acc[orow][3][q] += wv.w * xvv;
                        }
                }
            }
        }
        __syncthreads();   // all img reads done; safe to overwrite with h2
#pragma unroll
        for (int o = 0; o < 4; o++) {
            int oc = (tid / 18) * 4 + o;
            float inv = g2[oc] * rsqrtf(v2[oc] + 1e-5f);
            float sh = (b2[oc] - m2[oc]) * inv + be2[oc];
#pragma unroll
            for (int orow = 0; orow < 2; orow++)
#pragma unroll
                for (int q = 0; q < 4; q++)
                    h2[oc * 148 + (ry + orow) * 12 + cx + q] =
                        fmaxf(acc[orow][o][q] * inv + sh, 0.f);
        }
    }
    __syncthreads();

    // ---- phase B: h3 = h2 @ we^T + bee (broadcast, weights from L2) ----
    {
        int o_ = tid % 36, tc = tid / 36;        // tc 0..7
        int tb = tc * 8;
        const float4* h24 = (const float4*)h2;
        for (int o0 = 0; o0 < 144; o0 += 36) {
            int o = o0 + o_;
            const float4* w4 = (const float4*)&we[o * 144];
            float acc[8] = {};
            float4 wv = __ldg(&w4[0]);
            for (int k4 = 0; k4 < 36; k4++) {
                float4 wn = (k4 < 35) ? __ldg(&w4[k4 + 1]) : wv;
#pragma unroll
                for (int t = 0; t < 8; t++)
                    acc[t] += d4(h24[(tb + t) * 37 + k4], wv);
                wv = wn;
            }
            float bb = __ldg(&bee[o]);
#pragma unroll
            for (int t = 0; t < 8; t++)
                h3[(tb + t) * 148 + o] = acc[t] + bb;
        }
    }
    __syncthreads();

    // ---- phase C: h4 = wc2-mix(h3)+bc2 (4x4 tiles, weights from L2) ----
    for (int tt = tid; tt < 576; tt += 288) {
        int pt = tt % 36, lt = tt / 36;
        int p0 = pt * 4, lo0 = lt * 4;
        float a[4][4] = {};
        for (int li = 0; li < 64; li++) {
            float4 x4 = *(const float4*)&h3[li * 148 + p0];
            float w0 = __ldg(&wc2[(lo0 + 0) * 64 + li]);
            float w1v = __ldg(&wc2[(lo0 + 1) * 64 + li]);
            float w2v = __ldg(&wc2[(lo0 + 2) * 64 + li]);
            float w3v = __ldg(&wc2[(lo0 + 3) * 64 + li]);
            a[0][0] += w0 * x4.x; a[0][1] += w0 * x4.y; a[0][2] += w0 * x4.z; a[0][3] += w0 * x4.w;
            a[1][0] += w1v * x4.x; a[1][1] += w1v * x4.y; a[1][2] += w1v * x4.z; a[1][3] += w1v * x4.w;
            a[2][0] += w2v * x4.x; a[2][1] += w2v * x4.y; a[2][2] += w2v * x4.z; a[2][3] += w2v * x4.w;
            a[3][0] += w3v * x4.x; a[3][1] += w3v * x4.y; a[3][2] += w3v * x4.z; a[3][3] += w3v * x4.w;
        }
#pragma unroll
        for (int r = 0; r < 4; r++) {
            float bb = bc2[lo0 + r];
            float4 st = {a[r][0] + bb, a[r][1] + bb, a[r][2] + bb, a[r][3] + bb};
            *(float4*)&h4[(lo0 + r) * 148 + p0] = st;
            *(float4*)&g_h4[(size_t)bi * 9216 + (lo0 + r) * 144 + p0] = st;
        }
    }
    __syncthreads();

    // ---- phase D: xz = h4 @ in_w^T -> g_xz (broadcast, weights from L2) ----
    {
        int o_ = tid % 72, tc = tid / 72;        // tc 0..3
        int tb = tc * 16;
        const float4* h44 = (const float4*)h4;
        for (int o0 = 0; o0 < 576; o0 += 72) {
            int o = o0 + o_;
            const float4* w4 = (const float4*)&in_w[o * 144];
            float acc[16] = {};
            float4 wv = __ldg(&w4[0]);
            for (int k4 = 0; k4 < 36; k4++) {
                float4 wn = (k4 < 35) ? __ldg(&w4[k4 + 1]) : wv;
#pragma unroll
                for (int t = 0; t < 16; t++)
                    acc[t] += d4(h44[(tb + t) * 37 + k4], wv);
                wv = wn;
            }
#pragma unroll
            for (int t = 0; t < 16; t++)
                g_xz[(size_t)bi * 36864 + (tb + t) * 576 + o] = acc[t];
        }
    }
}

// ============ kernel 3: mamba + residual + wc3 + BN + ReLU ============
__global__ void __launch_bounds__(288, 2) k_mamba(
    const float* __restrict__ convd_w, const float* __restrict__ convd_b,
    const float* __restrict__ xproj_w, const float* __restrict__ dtproj_w,
    const float* __restrict__ dtproj_b, const float* __restrict__ A_log,
    const float* __restrict__ Dp, const float* __restrict__ out_w,
    const float* __restrict__ wc3, const float* __restrict__ bc3,
    const float* __restrict__ g3, const float* __restrict__ be3,
    const float* __restrict__ m3, const float* __restrict__ v3,
    float* __restrict__ out)
{
    extern __shared__ float sm[];
    float* uY = sm;                  // 18432
    float* dbl = sm + 18432;         // 3072 (overlaid by rS later)
    float* rS = sm + 18432;          // 9216
    int bi = blockIdx.x, c = threadIdx.x;
    const float* xzb = g_xz + (size_t)bi * 36864;

    {
        const float4* src = (const float4*)xzb;
        float4* dst = (float4*)uY;
        for (int i = c; i < 4608; i += 288) {
            int t = i / 72, ch4 = i - t * 72;
            dst[t * 72 + ch4] = src[t * 144 + ch4];
        }
    }
    __syncthreads();

    // depthwise causal conv (DC=4) + SiLU, in place, thread=channel
    {
        float cw0 = convd_w[c * 4], cw1 = convd_w[c * 4 + 1],
              cw2 = convd_w[c * 4 + 2], cw3 = convd_w[c * 4 + 3];
        float cb = convd_b[c];
        float p0 = 0.f, p1 = 0.f, p2 = 0.f;
        for (int t = 0; t < 64; t++) {
            float xt = uY[t * 288 + c];
            float s = cw0 * p0 + cw1 * p1 + cw2 * p2 + cw3 * xt + cb;
            s = s / (1.f + __expf(-s));
            uY[t * 288 + c] = s;
            p0 = p1; p1 = p2; p2 = xt;
        }
    }
    __syncthreads();

    // xproj (broadcast): thread = (tc 0..3, j 0..40), 16 t each
    if (c < 164) {
        int j = c % 41, tc = c / 41;
        float acc[16] = {};
        const float4* xw4 = (const float4*)&xproj_w[j * 288];
        const float4* uY4 = (const float4*)uY;
        int tb = tc * 16;
        float4 wv = __ldg(&xw4[0]);
        for (int k4 = 0; k4 < 72; k4++) {
            float4 wn = (k4 < 71) ? __ldg(&xw4[k4 + 1]) : wv;
#pragma unroll
            for (int t = 0; t < 16; t++)
                acc[t] += d4(uY4[(tb + t) * 72 + k4], wv);
            wv = wn;
        }
#pragma unroll
        for (int t = 0; t < 16; t++) dbl[(tb + t) * 48 + j] = acc[t];
    }
    __syncthreads();

    // selective scan + gate (thread=channel, 16 states in regs)
    {
        float dtw[9], A[16], h[16];
#pragma unroll
        for (int r = 0; r < 9; r++) dtw[r] = dtproj_w[c * 9 + r];
        float dtb = dtproj_b[c];
#pragma unroll
        for (int n = 0; n < 16; n++) { A[n] = -__expf(A_log[c * 16 + n]); h[n] = 0.f; }
        float dpc = Dp[c];
        for (int t = 0; t < 64; t++) {
            float zv = xzb[t * 576 + 288 + c];
            float dt = dtb;
#pragma unroll
            for (int r = 0; r < 9; r++) dt += dbl[t * 48 + r] * dtw[r];
            float delta = fmaxf(dt, 0.f) + log1pf(__expf(-fabsf(dt)));
            float u = uY[t * 288 + c];
            float dlu = delta * u;
            float y = 0.f;
#pragma unroll
            for (int n = 0; n < 16; n++) {
                float e = __expf(delta * A[n]);
                h[n] = h[n] * e + dlu * dbl[t * 48 + 9 + n];
                y += h[n] * dbl[t * 48 + 25 + n];
            }
            float sz = zv / (1.f + __expf(-zv));
            uY[t * 288 + c] = (y + u * dpc) * sz;
        }
    }
    __syncthreads();

    // out-proj (broadcast) + residual -> rS: thread = (tc 0..1, o 0..143), 32 t
    {
        int o = c % 144, tc = c / 144;
        float acc[32] = {};
        const float4* ow4 = (const float4*)&out_w[o * 288];
        const float4* uY4 = (const float4*)uY;
        int tb = tc * 32;
        float4 wv = __ldg(&ow4[0]);
        for (int k4 = 0; k4 < 72; k4++) {
            float4 wn = (k4 < 71) ? __ldg(&ow4[k4 + 1]) : wv;
#pragma unroll
            for (int t = 0; t < 32; t++)
                acc[t] += d4(uY4[(tb + t) * 72 + k4], wv);
            wv = wn;
        }
        const float* resb = g_h4 + (size_t)bi * 9216;
#pragma unroll
        for (int t = 0; t < 32; t++) {
            int tt = tb + t;
            rS[tt * 144 + o] = acc[t] + __ldg(&resb[tt * 144 + o]);
        }
    }
    __syncthreads();

    // wc3 (64->32 token mix) + BN + ReLU -> out, 4x4 tiles
    for (int i = c; i < 2048; i += 288) {
        int li = i >> 5, oc = i & 31;
        uY[i] = wc3[oc * 64 + li];
    }
    __syncthreads();
    {
        int pt = c % 36, ot = c / 36;
        int p0 = pt * 4, oc0 = ot * 4;
        float a[4][4] = {};
        for (int li = 0; li < 64; li++) {
            float4 w4 = *(const float4*)&uY[li * 32 + oc0];
            float4 x4 = *(const float4*)&rS[li * 144 + p0];
            a[0][0] += w4.x * x4.x; a[0][1] += w4.x * x4.y; a[0][2] += w4.x * x4.z; a[0][3] += w4.x * x4.w;
            a[1][0] += w4.y * x4.x; a[1][1] += w4.y * x4.y; a[1][2] += w4.y * x4.z; a[1][3] += w4.y * x4.w;
            a[2][0] += w4.z * x4.x; a[2][1] += w4.z * x4.y; a[2][2] += w4.z * x4.z; a[2][3] += w4.z * x4.w;
            a[3][0] += w4.w * x4.x; a[3][1] += w4.w * x4.y; a[3][2] += w4.w * x4.z; a[3][3] += w4.w * x4.w;
        }
#pragma unroll
        for (int r = 0; r < 4; r++) {
            int oc = oc0 + r;
            float inv = g3[oc] * rsqrtf(v3[oc] + 1e-5f);
            float sh = (bc3[oc] - m3[oc]) * inv + be3[oc];
            float4 st;
            st.x = fmaxf(a[r][0] * inv + sh, 0.f);
            st.y = fmaxf(a[r][1] * inv + sh, 0.f);
            st.z = fmaxf(a[r][2] * inv + sh, 0.f);
            st.w = fmaxf(a[r][3] * inv + sh, 0.f);
            *(float4*)&out[(size_t)bi * 4608 + oc * 144 + p0] = st;
        }
    }
}

extern "C" void kernel_launch(void* const* d_in, const int* in_sizes, int n_in,
                              void* d_out, int out_size)
{
    const float* x       = (const float*)d_in[0];
    const float* w1      = (const float*)d_in[1];
    const float* b1      = (const float*)d_in[2];
    const float* g1      = (const float*)d_in[3];
    const float* be1     = (const float*)d_in[4];
    const float* m1      = (const float*)d_in[5];
    const float* v1      = (const float*)d_in[6];
    const float* w2      = (const float*)d_in[7];
    const float* b2      = (const float*)d_in[8];
    const float* g2      = (const float*)d_in[9];
    const float* be2     = (const float*)d_in[10];
    const float* m2      = (const float*)d_in[11];
    const float* v2      = (const float*)d_in[12];
    const float* wc2     = (const float*)d_in[13];
    const float* bc2     = (const float*)d_in[14];
    const float* we      = (const float*)d_in[15];
    const float* bee     = (const float*)d_in[16];
    const float* in_w    = (const float*)d_in[17];
    const float* convd_w = (const float*)d_in[18];
    const float* convd_b = (const float*)d_in[19];
    const float* xproj_w = (const float*)d_in[20];
    const float* dtproj_w= (const float*)d_in[21];
    const float* dtproj_b= (const float*)d_in[22];
    const float* A_log   = (const float*)d_in[23];
    const float* Dp      = (const float*)d_in[24];
    const float* out_w   = (const float*)d_in[25];
    const float* wc3     = (const float*)d_in[26];
    const float* bc3     = (const float*)d_in[27];
    const float* g3      = (const float*)d_in[28];
    const float* be3     = (const float*)d_in[29];
    const float* m3      = (const float*)d_in[30];
    const float* v3      = (const float*)d_in[31];

    int B = in_sizes[0] / 28800;

    cudaFuncSetAttribute(k_mid, cudaFuncAttributeMaxDynamicSharedMemorySize, 75776);
    cudaFuncSetAttribute(k_mamba, cudaFuncAttributeMaxDynamicSharedMemorySize, 110592);

    k_front<<<B, 288>>>(x, w1);
    k_mid<<<B, 288, 75776>>>(g1, be1, m1, v1, b1,
                             w2, b2, g2, be2, m2, v2, wc2, bc2, we, bee, in_w);
    k_mamba<<<B, 288, 110592>>>(convd_w, convd_b, xproj_w, dtproj_w, dtproj_b,
                                A_log, Dp, out_w, wc3, bc3, g3, be3, m3, v3,
                                (float*)d_out);
}

// round 14
// speedup vs baseline: 1.3567x; 1.3567x over previous
#include <cuda_runtime.h>
#include <cuda_bf16.h>
#include <math.h>
#include <stdint.h>
#include <cstdint>

__device__ float g_h1[(size_t)512 * 32 * 144];
__device__ float g_h4[(size_t)512 * 64 * 144];
__device__ float g_xz[(size_t)512 * 64 * 576];
__device__ __align__(16) __nv_bfloat16 g_bH[576 * 144];
__device__ __align__(16) __nv_bfloat16 g_bL[576 * 144];

__device__ __forceinline__ float d4(float4 a, float4 b) {
    return a.x * b.x + a.y * b.y + a.z * b.z + a.w * b.w;
}

#define MMA_BF16(acc, a0, a1, a2, a3, b0, b1) \
    asm volatile("mma.sync.aligned.m16n8k16.row.col.f32.bf16.bf16.f32 " \
                 "{%0,%1,%2,%3}, {%4,%5,%6,%7}, {%8,%9}, {%0,%1,%2,%3};" \
                 : "+f"((acc)[0]), "+f"((acc)[1]), "+f"((acc)[2]), "+f"((acc)[3]) \
                 : "r"(a0), "r"(a1), "r"(a2), "r"(a3), "r"(b0), "r"(b1))

// ============ kernel 0: split in_w into packed bf16 hi/lo [576][144] ============
__global__ void k_prep(const float* __restrict__ in_w) {
    int i = blockIdx.x * blockDim.x + threadIdx.x;
    for (; i < 576 * 144; i += gridDim.x * blockDim.x) {
        float v = in_w[i];
        __nv_bfloat16 hi = __float2bfloat16(v);
        __nv_bfloat16 lo = __float2bfloat16(v - __bfloat162float(hi));
        g_bH[i] = hi;
        g_bL[i] = lo;
    }
}

// ============ kernel 1: conv1(200->32,3x3,pad1)+BN+ReLU (round-4) ============
__global__ void __launch_bounds__(288, 3) k_front(
    const float* __restrict__ x, const float* __restrict__ w1,
    const float* __restrict__ b1, const float* __restrict__ g1,
    const float* __restrict__ be1, const float* __restrict__ m1,
    const float* __restrict__ v1)
{
    __shared__ float xs[2][1568];
    __shared__ float ws[2304];
    int tid = threadIdx.x;
    int img = tid / 144, r = tid - img * 144;
    int pg = r % 18, ocg = r / 18;
    int ry = (pg / 3) * 2, cx = (pg % 3) * 4;
    size_t bi = (size_t)blockIdx.x * 2;
    float acc[2][4][4] = {};
    for (int i = tid; i < 2 * 1568; i += 288) ((float*)xs)[i] = 0.f;

    for (int c0 = 0; c0 < 200; c0 += 8) {
        __syncthreads();
        for (int i = tid; i < 2304; i += 288) {
            int im = i / 1152, j = i - im * 1152;
            int ic = j / 144, pos = j - ic * 144;
            int y = pos / 12, xx = pos - y * 12;
            xs[im][ic * 196 + (y + 1) * 14 + xx + 1] =
                x[(bi + im) * 28800 + (c0 + ic) * 144 + pos];
        }
        for (int i = tid; i < 2304; i += 288) {
            int ic = i / 288, rr = i - ic * 288;
            ws[i] = w1[(rr & 31) * 1800 + (c0 + ic) * 9 + (rr >> 5)];
        }
        __syncthreads();
#pragma unroll 1
        for (int ic = 0; ic < 8; ic++) {
            float xv[4][6];
            const float* xp = &xs[img][ic * 196 + ry * 14 + cx];
#pragma unroll
            for (int rr = 0; rr < 4; rr++)
#pragma unroll
                for (int cc = 0; cc < 6; cc++) xv[rr][cc] = xp[rr * 14 + cc];
#pragma unroll
            for (int k = 0; k < 9; k++) {
                float4 wv = *(const float4*)&ws[ic * 288 + k * 32 + ocg * 4];
                int kr = k / 3, kc = k % 3;
#pragma unroll
                for (int orow = 0; orow < 2; orow++)
#pragma unroll
                    for (int q = 0; q < 4; q++) {
                        float xvv = xv[orow + kr][kc + q];
                        acc[orow][0][q] += wv.x * xvv;
                        acc[orow][1][q] += wv.y * xvv;
                        acc[orow][2][q] += wv.z * xvv;
                        acc[orow][3][q] += wv.w * xvv;
                    }
            }
        }
    }
#pragma unroll
    for (int o = 0; o < 4; o++) {
        int oc = ocg * 4 + o;
        float inv = g1[oc] * rsqrtf(v1[oc] + 1e-5f);
        float sh = (b1[oc] - m1[oc]) * inv + be1[oc];
#pragma unroll
        for (int orow = 0; orow < 2; orow++) {
            float4 v;
            v.x = fmaxf(acc[orow][o][0] * inv + sh, 0.f);
            v.y = fmaxf(acc[orow][o][1] * inv + sh, 0.f);
            v.z = fmaxf(acc[orow][o][2] * inv + sh, 0.f);
            v.w = fmaxf(acc[orow][o][3] * inv + sh, 0.f);
            *(float4*)&g_h1[(bi + img) * 4608 + oc * 144 + (ry + orow) * 12 + cx] = v;
        }
    }
}

// ============ kernel 2: conv2+BN+ReLU -> we -> wc2 (round-4, phase D removed) ============
__global__ void __launch_bounds__(288, 2) k_mid(
    const float* __restrict__ w2, const float* __restrict__ b2,
    const float* __restrict__ g2, const float* __restrict__ be2,
    const float* __restrict__ m2, const float* __restrict__ v2,
    const float* __restrict__ wc2, const float* __restrict__ bc2,
    const float* __restrict__ we, const float* __restrict__ bee)
{
    extern __shared__ float sm[];
    float* ws2 = sm;
    float* img = sm + 4608;
    float* stage = sm;
    float* h3 = sm + 9216;
    float* h2 = sm + 18688;
    int bi = blockIdx.x, tid = threadIdx.x;

    for (int i = tid; i < 6272; i += 288) img[i] = 0.f;
    __syncthreads();
    for (int i = tid; i < 4608; i += 288) {
        int ic = i / 144, pos = i - ic * 144;
        int y = pos / 12, xx = pos - y * 12;
        img[ic * 196 + (y + 1) * 14 + xx + 1] = g_h1[(size_t)bi * 4608 + i];
    }
    {
        int pg = tid % 18, ocg = tid / 18;
        int ry = (pg / 3) * 2, cx = (pg % 3) * 4;
        float acc[2][4][4] = {};
        for (int c0 = 0; c0 < 32; c0 += 8) {
            __syncthreads();
            for (int i = tid; i < 4608; i += 288) {
                int ic = i / 576, rr = i - ic * 576;
                ws2[i] = w2[(rr & 63) * 288 + (c0 + ic) * 9 + (rr >> 6)];
            }
            __syncthreads();
#pragma unroll 1
            for (int ic = 0; ic < 8; ic++) {
                float xv[4][6];
                const float* xp = &img[(c0 + ic) * 196 + ry * 14 + cx];
#pragma unroll
                for (int rr = 0; rr < 4; rr++)
#pragma unroll
                    for (int cc = 0; cc < 6; cc++) xv[rr][cc] = xp[rr * 14 + cc];
#pragma unroll
                for (int k = 0; k < 9; k++) {
                    float4 wv = *(const float4*)&ws2[ic * 576 + k * 64 + ocg * 4];
                    int kr = k / 3, kc = k % 3;
#pragma unroll
                    for (int orow = 0; orow < 2; orow++)
#pragma unroll
                        for (int q = 0; q < 4; q++) {
                            float xvv = xv[orow + kr][kc + q];
                            acc[orow][0][q] += wv.x * xvv;
                            acc[orow][1][q] += wv.y * xvv;
                            acc[orow][2][q] += wv.z * xvv;
                            acc[orow][3][q] += wv.w * xvv;
                        }
                }
            }
        }
        __syncthreads();
#pragma unroll
        for (int o = 0; o < 4; o++) {
            int oc = (tid / 18) * 4 + o;
            float inv = g2[oc] * rsqrtf(v2[oc] + 1e-5f);
            float sh = (b2[oc] - m2[oc]) * inv + be2[oc];
#pragma unroll
            for (int orow = 0; orow < 2; orow++)
#pragma unroll
                for (int q = 0; q < 4; q++)
                    h2[oc * 148 + (ry + orow) * 12 + cx + q] =
                        fmaxf(acc[orow][o][q] * inv + sh, 0.f);
        }
    }

    // phase B: h3 = h2 @ we^T + bee (broadcast, 48-o chunks)
    {
        int oslot = tid % 48, tc = tid / 48;
        const float4* h24 = (const float4*)h2;
        for (int o0 = 0; o0 < 144; o0 += 48) {
            __syncthreads();
            for (int i = tid; i < 48 * 144; i += 288) {
                int o = i / 144, k = i - o * 144;
                stage[o * 148 + k] = we[(o0 + o) * 144 + k];
            }
            __syncthreads();
            if (tid < 192) {
                float acc[16] = {};
                const float4* w4 = (const float4*)&stage[oslot * 148];
                int tb = tc * 16;
                for (int k4 = 0; k4 < 36; k4++) {
                    float4 wv = w4[k4];
#pragma unroll
                    for (int t = 0; t < 16; t++)
                        acc[t] += d4(h24[(tb + t) * 37 + k4], wv);
                }
                float bb = bee[o0 + oslot];
#pragma unroll
                for (int t = 0; t < 16; t++)
                    h3[(tb + t) * 148 + o0 + oslot] = acc[t] + bb;
            }
        }
    }

    // phase C: h4 = wc2-mix(h3)+bc2 -> g_h4
    __syncthreads();
    for (int i = tid; i < 4096; i += 288) {
        int li = i >> 6, lo = i & 63;
        stage[i] = wc2[lo * 64 + li];
    }
    __syncthreads();
    for (int tt = tid; tt < 576; tt += 288) {
        int pt = tt % 36, lt = tt / 36;
        int p0 = pt * 4, lo0 = lt * 4;
        float a[4][4] = {};
        for (int li = 0; li < 64; li++) {
            float4 w4 = *(const float4*)&stage[li * 64 + lo0];
            float4 x4 = *(const float4*)&h3[li * 148 + p0];
            a[0][0] += w4.x * x4.x; a[0][1] += w4.x * x4.y; a[0][2] += w4.x * x4.z; a[0][3] += w4.x * x4.w;
            a[1][0] += w4.y * x4.x; a[1][1] += w4.y * x4.y; a[1][2] += w4.y * x4.z; a[1][3] += w4.y * x4.w;
            a[2][0] += w4.z * x4.x; a[2][1] += w4.z * x4.y; a[2][2] += w4.z * x4.z; a[2][3] += w4.z * x4.w;
            a[3][0] += w4.w * x4.x; a[3][1] += w4.w * x4.y; a[3][2] += w4.w * x4.z; a[3][3] += w4.w * x4.w;
        }
#pragma unroll
        for (int r = 0; r < 4; r++) {
            float bb = bc2[lo0 + r];
            float4 st = {a[r][0] + bb, a[r][1] + bb, a[r][2] + bb, a[r][3] + bb};
            *(float4*)&g_h4[(size_t)bi * 9216 + (lo0 + r) * 144 + p0] = st;
        }
    }
}

// ============ kernel 2.5: xz = h4 @ in_w^T via mma.sync bf16-split ============
// 1 image/CTA (M=64), 256 threads = 8 warps; warp = (mtile 0..3, nhalf 0..1)
// SMEM: Ah[64][168] @0, Al @21504, Bh[64][152] @43008, Bl @62464 (bytes); total 81920
__global__ void __launch_bounds__(256, 2) k_proj() {
    extern __shared__ unsigned char smp[];
    __nv_bfloat16* Ah = (__nv_bfloat16*)smp;
    __nv_bfloat16* Al = (__nv_bfloat16*)(smp + 21504);
    __nv_bfloat16* Bh = (__nv_bfloat16*)(smp + 43008);
    __nv_bfloat16* Bl = (__nv_bfloat16*)(smp + 62464);
    int tid = threadIdx.x, wid = tid >> 5, lane = tid & 31;
    int gid = lane >> 2, tid4 = lane & 3;
    size_t bi = blockIdx.x;
    const float* h4 = g_h4 + bi * 9216;

    // stage A: fp32 -> bf16 hi/lo, row stride 168 (conflict-free)
    for (int i = tid; i < 9216; i += 256) {
        int r = i / 144, c = i - r * 144;
        float v = h4[i];
        __nv_bfloat16 hi = __float2bfloat16(v);
        __nv_bfloat16 lo = __float2bfloat16(v - __bfloat162float(hi));
        Ah[r * 168 + c] = hi;
        Al[r * 168 + c] = lo;
    }

    int mtile = wid >> 1, nhalf = wid & 1;
    int m0 = mtile * 16 + gid;
    float* dst = g_xz + bi * 36864;

    for (int chunk = 0; chunk < 9; chunk++) {
        __syncthreads();   // A ready (first iter) / prev chunk's B reads done
        {   // stage B chunk: rows o = chunk*64.., 144 bf16 = 18 uint4 per row
            const uint4* sH = (const uint4*)(g_bH + chunk * 64 * 144);
            const uint4* sL = (const uint4*)(g_bL + chunk * 64 * 144);
            for (int i = tid; i < 1152; i += 256) {
                int row = i / 18, w = i - row * 18;
                ((uint4*)Bh)[row * 19 + w] = sH[i];
                ((uint4*)Bl)[row * 19 + w] = sL[i];
            }
        }
        __syncthreads();

        float acc[4][4] = {};
#pragma unroll 1
        for (int k = 0; k < 9; k++) {
            int ac = k * 16 + tid4 * 2;
            uint32_t aH0 = *(const uint32_t*)&Ah[m0 * 168 + ac];
            uint32_t aH1 = *(const uint32_t*)&Ah[(m0 + 8) * 168 + ac];
            uint32_t aH2 = *(const uint32_t*)&Ah[m0 * 168 + ac + 8];
            uint32_t aH3 = *(const uint32_t*)&Ah[(m0 + 8) * 168 + ac + 8];
            uint32_t aL0 = *(const uint32_t*)&Al[m0 * 168 + ac];
            uint32_t aL1 = *(const uint32_t*)&Al[(m0 + 8) * 168 + ac];
            uint32_t aL2 = *(const uint32_t*)&Al[m0 * 168 + ac + 8];
            uint32_t aL3 = *(const uint32_t*)&Al[(m0 + 8) * 168 + ac + 8];
#pragma unroll
            for (int nt = 0; nt < 4; nt++) {
                int o = nhalf * 32 + nt * 8 + gid;
                uint32_t bH0 = *(const uint32_t*)&Bh[o * 152 + ac];
                uint32_t bH1 = *(const uint32_t*)&Bh[o * 152 + ac + 8];
                uint32_t bL0 = *(const uint32_t*)&Bl[o * 152 + ac];
                uint32_t bL1 = *(const uint32_t*)&Bl[o * 152 + ac + 8];
                MMA_BF16(acc[nt], aH0, aH1, aH2, aH3, bH0, bH1);
                MMA_BF16(acc[nt], aH0, aH1, aH2, aH3, bL0, bL1);
                MMA_BF16(acc[nt], aL0, aL1, aL2, aL3, bH0, bH1);
            }
        }
#pragma unroll
        for (int nt = 0; nt < 4; nt++) {
            int col = chunk * 64 + nhalf * 32 + nt * 8 + tid4 * 2;
            float2 v01 = {acc[nt][0], acc[nt][1]};
            float2 v23 = {acc[nt][2], acc[nt][3]};
            *(float2*)&dst[(size_t)m0 * 576 + col] = v01;
            *(float2*)&dst[(size_t)(m0 + 8) * 576 + col] = v23;
        }
    }
}

// ============ kernel 3: mamba + residual + wc3 + BN + ReLU (round-4) ============
__global__ void __launch_bounds__(288, 2) k_mamba(
    const float* __restrict__ convd_w, const float* __restrict__ convd_b,
    const float* __restrict__ xproj_w, const float* __restrict__ dtproj_w,
    const float* __restrict__ dtproj_b, const float* __restrict__ A_log,
    const float* __restrict__ Dp, const float* __restrict__ out_w,
    const float* __restrict__ wc3, const float* __restrict__ bc3,
    const float* __restrict__ g3, const float* __restrict__ be3,
    const float* __restrict__ m3, const float* __restrict__ v3,
    float* __restrict__ out)
{
    extern __shared__ float sm[];
    float* uY = sm;
    float* dbl = sm + 18432;
    float* rS = sm + 18432;
    int bi = blockIdx.x, c = threadIdx.x;
    const float* xzb = g_xz + (size_t)bi * 36864;

    {
        const float4* src = (const float4*)xzb;
        float4* dst = (float4*)uY;
        for (int i = c; i < 4608; i += 288) {
            int t = i / 72, ch4 = i - t * 72;
            dst[t * 72 + ch4] = src[t * 144 + ch4];
        }
    }
    __syncthreads();

    {
        float cw0 = convd_w[c * 4], cw1 = convd_w[c * 4 + 1],
              cw2 = convd_w[c * 4 + 2], cw3 = convd_w[c * 4 + 3];
        float cb = convd_b[c];
        float p0 = 0.f, p1 = 0.f, p2 = 0.f;
        for (int t = 0; t < 64; t++) {
            float xt = uY[t * 288 + c];
            float s = cw0 * p0 + cw1 * p1 + cw2 * p2 + cw3 * xt + cb;
            s = s / (1.f + __expf(-s));
            uY[t * 288 + c] = s;
            p0 = p1; p1 = p2; p2 = xt;
        }
    }
    __syncthreads();

    if (c < 164) {
        int j = c % 41, tc = c / 41;
        float acc[16] = {};
        const float4* xw4 = (const float4*)&xproj_w[j * 288];
        const float4* uY4 = (const float4*)uY;
        int tb = tc * 16;
        float4 wv = __ldg(&xw4[0]);
        for (int k4 = 0; k4 < 72; k4++) {
            float4 wn = (k4 < 71) ? __ldg(&xw4[k4 + 1]) : wv;
#pragma unroll
            for (int t = 0; t < 16; t++)
                acc[t] += d4(uY4[(tb + t) * 72 + k4], wv);
            wv = wn;
        }
#pragma unroll
        for (int t = 0; t < 16; t++) dbl[(tb + t) * 48 + j] = acc[t];
    }
    __syncthreads();

    {
        float dtw[9], A[16], h[16];
#pragma unroll
        for (int r = 0; r < 9; r++) dtw[r] = dtproj_w[c * 9 + r];
        float dtb = dtproj_b[c];
#pragma unroll
        for (int n = 0; n < 16; n++) { A[n] = -__expf(A_log[c * 16 + n]); h[n] = 0.f; }
        float dpc = Dp[c];
        for (int t = 0; t < 64; t++) {
            float zv = xzb[t * 576 + 288 + c];
            float dt = dtb;
#pragma unroll
            for (int r = 0; r < 9; r++) dt += dbl[t * 48 + r] * dtw[r];
            float delta = fmaxf(dt, 0.f) + log1pf(__expf(-fabsf(dt)));
            float u = uY[t * 288 + c];
            float dlu = delta * u;
            float y = 0.f;
#pragma unroll
            for (int n = 0; n < 16; n++) {
                float e = __expf(delta * A[n]);
                h[n] = h[n] * e + dlu * dbl[t * 48 + 9 + n];
                y += h[n] * dbl[t * 48 + 25 + n];
            }
            float sz = zv / (1.f + __expf(-zv));
            uY[t * 288 + c] = (y + u * dpc) * sz;
        }
    }
    __syncthreads();

    {
        int o = c % 144, tc = c / 144;
        float acc[32] = {};
        const float4* ow4 = (const float4*)&out_w[o * 288];
        const float4* uY4 = (const float4*)uY;
        int tb = tc * 32;
        float4 wv = __ldg(&ow4[0]);
        for (int k4 = 0; k4 < 72; k4++) {
            float4 wn = (k4 < 71) ? __ldg(&ow4[k4 + 1]) : wv;
#pragma unroll
            for (int t = 0; t < 32; t++)
                acc[t] += d4(uY4[(tb + t) * 72 + k4], wv);
            wv = wn;
        }
        const float* resb = g_h4 + (size_t)bi * 9216;
#pragma unroll
        for (int t = 0; t < 32; t++) {
            int tt = tb + t;
            rS[tt * 144 + o] = acc[t] + __ldg(&resb[tt * 144 + o]);
        }
    }
    __syncthreads();

    for (int i = c; i < 2048; i += 288) {
        int li = i >> 5, oc = i & 31;
        uY[i] = wc3[oc * 64 + li];
    }
    __syncthreads();
    {
        int pt = c % 36, ot = c / 36;
        int p0 = pt * 4, oc0 = ot * 4;
        float a[4][4] = {};
        for (int li = 0; li < 64; li++) {
            float4 w4 = *(const float4*)&uY[li * 32 + oc0];
            float4 x4 = *(const float4*)&rS[li * 144 + p0];
            a[0][0] += w4.x * x4.x; a[0][1] += w4.x * x4.y; a[0][2] += w4.x * x4.z; a[0][3] += w4.x * x4.w;
            a[1][0] += w4.y * x4.x; a[1][1] += w4.y * x4.y; a[1][2] += w4.y * x4.z; a[1][3] += w4.y * x4.w;
            a[2][0] += w4.z * x4.x; a[2][1] += w4.z * x4.y; a[2][2] += w4.z * x4.z; a[2][3] += w4.z * x4.w;
            a[3][0] += w4.w * x4.x; a[3][1] += w4.w * x4.y; a[3][2] += w4.w * x4.z; a[3][3] += w4.w * x4.w;
        }
#pragma unroll
        for (int r = 0; r < 4; r++) {
            int oc = oc0 + r;
            float inv = g3[oc] * rsqrtf(v3[oc] + 1e-5f);
            float sh = (bc3[oc] - m3[oc]) * inv + be3[oc];
            float4 st;
            st.x = fmaxf(a[r][0] * inv + sh, 0.f);
            st.y = fmaxf(a[r][1] * inv + sh, 0.f);
            st.z = fmaxf(a[r][2] * inv + sh, 0.f);
            st.w = fmaxf(a[r][3] * inv + sh, 0.f);
            *(float4*)&out[(size_t)bi * 4608 + oc * 144 + p0] = st;
        }
    }
}

extern "C" void kernel_launch(void* const* d_in, const int* in_sizes, int n_in,
                              void* d_out, int out_size)
{
    const float* x       = (const float*)d_in[0];
    const float* w1      = (const float*)d_in[1];
    const float* b1      = (const float*)d_in[2];
    const float* g1      = (const float*)d_in[3];
    const float* be1     = (const float*)d_in[4];
    const float* m1      = (const float*)d_in[5];
    const float* v1      = (const float*)d_in[6];
    const float* w2      = (const float*)d_in[7];
    const float* b2      = (const float*)d_in[8];
    const float* g2      = (const float*)d_in[9];
    const float* be2     = (const float*)d_in[10];
    const float* m2      = (const float*)d_in[11];
    const float* v2      = (const float*)d_in[12];
    const float* wc2     = (const float*)d_in[13];
    const float* bc2     = (const float*)d_in[14];
    const float* we      = (const float*)d_in[15];
    const float* bee     = (const float*)d_in[16];
    const float* in_w    = (const float*)d_in[17];
    const float* convd_w = (const float*)d_in[18];
    const float* convd_b = (const float*)d_in[19];
    const float* xproj_w = (const float*)d_in[20];
    const float* dtproj_w= (const float*)d_in[21];
    const float* dtproj_b= (const float*)d_in[22];
    const float* A_log   = (const float*)d_in[23];
    const float* Dp      = (const float*)d_in[24];
    const float* out_w   = (const float*)d_in[25];
    const float* wc3     = (const float*)d_in[26];
    const float* bc3     = (const float*)d_in[27];
    const float* g3      = (const float*)d_in[28];
    const float* be3     = (const float*)d_in[29];
    const float* m3      = (const float*)d_in[30];
    const float* v3      = (const float*)d_in[31];

    int B = in_sizes[0] / 28800;

    cudaFuncSetAttribute(k_mid, cudaFuncAttributeMaxDynamicSharedMemorySize, 112640);
    cudaFuncSetAttribute(k_proj, cudaFuncAttributeMaxDynamicSharedMemorySize, 81920);
    cudaFuncSetAttribute(k_mamba, cudaFuncAttributeMaxDynamicSharedMemorySize, 110592);

    k_prep<<<108, 256>>>(in_w);
    k_front<<<B / 2, 288>>>(x, w1, b1, g1, be1, m1, v1);
    k_mid<<<B, 288, 112640>>>(w2, b2, g2, be2, m2, v2, wc2, bc2, we, bee);
    k_proj<<<B, 256, 81920>>>();
    k_mamba<<<B, 288, 110592>>>(convd_w, convd_b, xproj_w, dtproj_w, dtproj_b,
                                A_log, Dp, out_w, wc3, bc3, g3, be3, m3, v3,
                                (float*)d_out);
}

// round 16
// speedup vs baseline: 1.5027x; 1.1076x over previous
#include <cuda_runtime.h>
#include <cuda_bf16.h>
#include <math.h>
#include <stdint.h>
#include <cstdint>

__device__ float g_h1[(size_t)512 * 32 * 144];
__device__ float g_h4[(size_t)512 * 64 * 144];
__device__ float g_xz[(size_t)512 * 64 * 576];
__device__ __align__(16) __nv_bfloat16 g_bH[576 * 144];
__device__ __align__(16) __nv_bfloat16 g_bL[576 * 144];

__device__ __forceinline__ float d4(float4 a, float4 b) {
    return a.x * b.x + a.y * b.y + a.z * b.z + a.w * b.w;
}

#define MMA_BF16(acc, a0, a1, a2, a3, b0, b1) \
    asm volatile("mma.sync.aligned.m16n8k16.row.col.f32.bf16.bf16.f32 " \
                 "{%0,%1,%2,%3}, {%4,%5,%6,%7}, {%8,%9}, {%0,%1,%2,%3};" \
                 : "+f"((acc)[0]), "+f"((acc)[1]), "+f"((acc)[2]), "+f"((acc)[3]) \
                 : "r"(a0), "r"(a1), "r"(a2), "r"(a3), "r"(b0), "r"(b1))

// ============ kernel 0: split in_w into packed bf16 hi/lo [576][144] ============
__global__ void k_prep(const float* __restrict__ in_w) {
    int i = blockIdx.x * blockDim.x + threadIdx.x;
    for (; i < 576 * 144; i += gridDim.x * blockDim.x) {
        float v = in_w[i];
        __nv_bfloat16 hi = __float2bfloat16(v);
        __nv_bfloat16 lo = __float2bfloat16(v - __bfloat162float(hi));
        g_bH[i] = hi;
        g_bL[i] = lo;
    }
}

// ============ kernel 1: conv1(200->32,3x3,pad1)+BN+ReLU via mma.sync ============
// implicit GEMM, tap-major K: step = (ic-chunk of 16, tap). A = padded image
// stored [pixel][ic] bf16 hi/lo (shifted reads, no im2col). 9 warps = 9 m16 tiles.
__global__ void __launch_bounds__(288, 3) k_front(
    const float* __restrict__ x, const float* __restrict__ w1,
    const float* __restrict__ b1, const float* __restrict__ g1,
    const float* __restrict__ be1, const float* __restrict__ m1,
    const float* __restrict__ v1)
{
    __shared__ __nv_bfloat16 iTh[196 * 16], iTl[196 * 16];   // [pix][ic]
    __shared__ __nv_bfloat16 wTh[9 * 32 * 16], wTl[9 * 32 * 16]; // [tap][oc][ic]
    int tid = threadIdx.x, wid = tid >> 5, lane = tid & 31;
    int gid = lane >> 2, tid4 = lane & 3;
    size_t bi = blockIdx.x;
    const float* xb = x + bi * 28800;

    for (int i = tid; i < 196 * 16; i += 288) { iTh[i] = __float2bfloat16(0.f); iTl[i] = __float2bfloat16(0.f); }

    // rows handled by this warp: r0 = wid*16+gid, r1 = r0+8
    int r0 = wid * 16 + gid, r1 = r0 + 8;
    int y0 = r0 / 12, x0 = r0 - y0 * 12;
    int y1 = r1 / 12, x1 = r1 - y1 * 12;
    float acc[4][4] = {};

    for (int chunk = 0; chunk < 13; chunk++) {
        __syncthreads();
        // stage input chunk: 16 ic x 144 pos -> [pix][ic]
        for (int i = tid; i < 2304; i += 288) {
            int ici = i / 144, pos = i - ici * 144;
            int ic = chunk * 16 + ici;
            float v = (ic < 200) ? xb[ic * 144 + pos] : 0.f;
            int yy = pos / 12, xx = pos - yy * 12;
            int idx = ((yy + 1) * 14 + xx + 1) * 16 + ici;
            __nv_bfloat16 hi = __float2bfloat16(v);
            iTh[idx] = hi;
            iTl[idx] = __float2bfloat16(v - __bfloat162float(hi));
        }
        // stage weights: [tap][oc][ic]
        for (int i = tid; i < 4608; i += 288) {
            int tap = i >> 9, rem = i & 511;
            int oc = rem >> 4, ici = rem & 15;
            int ic = chunk * 16 + ici;
            float v = (ic < 200) ? w1[oc * 1800 + ic * 9 + tap] : 0.f;
            __nv_bfloat16 hi = __float2bfloat16(v);
            wTh[i] = hi;
            wTl[i] = __float2bfloat16(v - __bfloat162float(hi));
        }
        __syncthreads();
#pragma unroll 1
        for (int tap = 0; tap < 9; tap++) {
            int dy = tap / 3, dx = tap - dy * 3;
            int p0 = ((y0 + dy) * 14 + x0 + dx) * 16 + tid4 * 2;
            int p1 = ((y1 + dy) * 14 + x1 + dx) * 16 + tid4 * 2;
            uint32_t aH0 = *(const uint32_t*)&iTh[p0];
            uint32_t aH1 = *(const uint32_t*)&iTh[p1];
            uint32_t aH2 = *(const uint32_t*)&iTh[p0 + 8];
            uint32_t aH3 = *(const uint32_t*)&iTh[p1 + 8];
            uint32_t aL0 = *(const uint32_t*)&iTl[p0];
            uint32_t aL1 = *(const uint32_t*)&iTl[p1];
            uint32_t aL2 = *(const uint32_t*)&iTl[p0 + 8];
            uint32_t aL3 = *(const uint32_t*)&iTl[p1 + 8];
#pragma unroll
            for (int nt = 0; nt < 4; nt++) {
                int wb = (tap * 32 + nt * 8 + gid) * 16 + tid4 * 2;
                uint32_t bH0 = *(const uint32_t*)&wTh[wb];
                uint32_t bH1 = *(const uint32_t*)&wTh[wb + 8];
                uint32_t bL0 = *(const uint32_t*)&wTl[wb];
                uint32_t bL1 = *(const uint32_t*)&wTl[wb + 8];
                MMA_BF16(acc[nt], aH0, aH1, aH2, aH3, bH0, bH1);
                MMA_BF16(acc[nt], aH0, aH1, aH2, aH3, bL0, bL1);
                MMA_BF16(acc[nt], aL0, aL1, aL2, aL3, bH0, bH1);
            }
        }
    }
    // epilogue: BN + ReLU, scatter to g_h1[oc*144 + pos]
#pragma unroll
    for (int nt = 0; nt < 4; nt++) {
        int oc0 = nt * 8 + tid4 * 2;
#pragma unroll
        for (int cc = 0; cc < 2; cc++) {
            int oc = oc0 + cc;
            float inv = g1[oc] * rsqrtf(v1[oc] + 1e-5f);
            float sh = (b1[oc] - m1[oc]) * inv + be1[oc];
            g_h1[bi * 4608 + oc * 144 + r0] = fmaxf(acc[nt][cc] * inv + sh, 0.f);
            g_h1[bi * 4608 + oc * 144 + r1] = fmaxf(acc[nt][2 + cc] * inv + sh, 0.f);
        }
    }
}

// ============ kernel 2: conv2+BN+ReLU -> we -> wc2 (round-14) ============
__global__ void __launch_bounds__(288, 2) k_mid(
    const float* __restrict__ w2, const float* __restrict__ b2,
    const float* __restrict__ g2, const float* __restrict__ be2,
    const float* __restrict__ m2, const float* __restrict__ v2,
    const float* __restrict__ wc2, const float* __restrict__ bc2,
    const float* __restrict__ we, const float* __restrict__ bee)
{
    extern __shared__ float sm[];
    float* ws2 = sm;
    float* img = sm + 4608;
    float* stage = sm;
    float* h3 = sm + 9216;
    float* h2 = sm + 18688;
    int bi = blockIdx.x, tid = threadIdx.x;

    for (int i = tid; i < 6272; i += 288) img[i] = 0.f;
    __syncthreads();
    for (int i = tid; i < 4608; i += 288) {
        int ic = i / 144, pos = i - ic * 144;
        int y = pos / 12, xx = pos - y * 12;
        img[ic * 196 + (y + 1) * 14 + xx + 1] = g_h1[(size_t)bi * 4608 + i];
    }
    {
        int pg = tid % 18, ocg = tid / 18;
        int ry = (pg / 3) * 2, cx = (pg % 3) * 4;
        float acc[2][4][4] = {};
        for (int c0 = 0; c0 < 32; c0 += 8) {
            __syncthreads();
            for (int i = tid; i < 4608; i += 288) {
                int ic = i / 576, rr = i - ic * 576;
                ws2[i] = w2[(rr & 63) * 288 + (c0 + ic) * 9 + (rr >> 6)];
            }
            __syncthreads();
#pragma unroll 1
            for (int ic = 0; ic < 8; ic++) {
                float xv[4][6];
                const float* xp = &img[(c0 + ic) * 196 + ry * 14 + cx];
#pragma unroll
                for (int rr = 0; rr < 4; rr++)
#pragma unroll
                    for (int cc = 0; cc < 6; cc++) xv[rr][cc] = xp[rr * 14 + cc];
#pragma unroll
                for (int k = 0; k < 9; k++) {
                    float4 wv = *(const float4*)&ws2[ic * 576 + k * 64 + ocg * 4];
                    int kr = k / 3, kc = k % 3;
#pragma unroll
                    for (int orow = 0; orow < 2; orow++)
#pragma unroll
                        for (int q = 0; q < 4; q++) {
                            float xvv = xv[orow + kr][kc + q];
                            acc[orow][0][q] += wv.x * xvv;
                            acc[orow][1][q] += wv.y * xvv;
                            acc[orow][2][q] += wv.z * xvv;
                            acc[orow][3][q] += wv.w * xvv;
                        }
                }
            }
        }
        __syncthreads();
#pragma unroll
        for (int o = 0; o < 4; o++) {
            int oc = (tid / 18) * 4 + o;
            float inv = g2[oc] * rsqrtf(v2[oc] + 1e-5f);
            float sh = (b2[oc] - m2[oc]) * inv + be2[oc];
#pragma unroll
            for (int orow = 0; orow < 2; orow++)
#pragma unroll
                for (int q = 0; q < 4; q++)
                    h2[oc * 148 + (ry + orow) * 12 + cx + q] =
                        fmaxf(acc[orow][o][q] * inv + sh, 0.f);
        }
    }

    // phase B: h3 = h2 @ we^T + bee (broadcast, 48-o chunks)
    {
        int oslot = tid % 48, tc = tid / 48;
        const float4* h24 = (const float4*)h2;
        for (int o0 = 0; o0 < 144; o0 += 48) {
            __syncthreads();
            for (int i = tid; i < 48 * 144; i += 288) {
                int o = i / 144, k = i - o * 144;
                stage[o * 148 + k] = we[(o0 + o) * 144 + k];
            }
            __syncthreads();
            if (tid < 192) {
                float acc[16] = {};
                const float4* w4 = (const float4*)&stage[oslot * 148];
                int tb = tc * 16;
                for (int k4 = 0; k4 < 36; k4++) {
                    float4 wv = w4[k4];
#pragma unroll
                    for (int t = 0; t < 16; t++)
                        acc[t] += d4(h24[(tb + t) * 37 + k4], wv);
                }
                float bb = bee[o0 + oslot];
#pragma unroll
                for (int t = 0; t < 16; t++)
                    h3[(tb + t) * 148 + o0 + oslot] = acc[t] + bb;
            }
        }
    }

    // phase C: h4 = wc2-mix(h3)+bc2 -> g_h4
    __syncthreads();
    for (int i = tid; i < 4096; i += 288) {
        int li = i >> 6, lo = i & 63;
        stage[i] = wc2[lo * 64 + li];
    }
    __syncthreads();
    for (int tt = tid; tt < 576; tt += 288) {
        int pt = tt % 36, lt = tt / 36;
        int p0 = pt * 4, lo0 = lt * 4;
        float a[4][4] = {};
        for (int li = 0; li < 64; li++) {
            float4 w4 = *(const float4*)&stage[li * 64 + lo0];
            float4 x4 = *(const float4*)&h3[li * 148 + p0];
            a[0][0] += w4.x * x4.x; a[0][1] += w4.x * x4.y; a[0][2] += w4.x * x4.z; a[0][3] += w4.x * x4.w;
            a[1][0] += w4.y * x4.x; a[1][1] += w4.y * x4.y; a[1][2] += w4.y * x4.z; a[1][3] += w4.y * x4.w;
            a[2][0] += w4.z * x4.x; a[2][1] += w4.z * x4.y; a[2][2] += w4.z * x4.z; a[2][3] += w4.z * x4.w;
            a[3][0] += w4.w * x4.x; a[3][1] += w4.w * x4.y; a[3][2] += w4.w * x4.z; a[3][3] += w4.w * x4.w;
        }
#pragma unroll
        for (int r = 0; r < 4; r++) {
            float bb = bc2[lo0 + r];
            float4 st = {a[r][0] + bb, a[r][1] + bb, a[r][2] + bb, a[r][3] + bb};
            *(float4*)&g_h4[(size_t)bi * 9216 + (lo0 + r) * 144 + p0] = st;
        }
    }
}

// ============ kernel 2.5: xz = h4 @ in_w^T via mma.sync bf16-split (round-14) ============
__global__ void __launch_bounds__(256, 2) k_proj() {
    extern __shared__ unsigned char smp[];
    __nv_bfloat16* Ah = (__nv_bfloat16*)smp;
    __nv_bfloat16* Al = (__nv_bfloat16*)(smp + 21504);
    __nv_bfloat16* Bh = (__nv_bfloat16*)(smp + 43008);
    __nv_bfloat16* Bl = (__nv_bfloat16*)(smp + 62464);
    int tid = threadIdx.x, wid = tid >> 5, lane = tid & 31;
    int gid = lane >> 2, tid4 = lane & 3;
    size_t bi = blockIdx.x;
    const float* h4 = g_h4 + bi * 9216;

    for (int i = tid; i < 9216; i += 256) {
        int r = i / 144, c = i - r * 144;
        float v = h4[i];
        __nv_bfloat16 hi = __float2bfloat16(v);
        __nv_bfloat16 lo = __float2bfloat16(v - __bfloat162float(hi));
        Ah[r * 168 + c] = hi;
        Al[r * 168 + c] = lo;
    }

    int mtile = wid >> 1, nhalf = wid & 1;
    int m0 = mtile * 16 + gid;
    float* dst = g_xz + bi * 36864;

    for (int chunk = 0; chunk < 9; chunk++) {
        __syncthreads();
        {
            const uint4* sH = (const uint4*)(g_bH + chunk * 64 * 144);
            const uint4* sL = (const uint4*)(g_bL + chunk * 64 * 144);
            for (int i = tid; i < 1152; i += 256) {
                int row = i / 18, w = i - row * 18;
                ((uint4*)Bh)[row * 19 + w] = sH[i];
                ((uint4*)Bl)[row * 19 + w] = sL[i];
            }
        }
        __syncthreads();

        float acc[4][4] = {};
#pragma unroll 1
        for (int k = 0; k < 9; k++) {
            int ac = k * 16 + tid4 * 2;
            uint32_t aH0 = *(const uint32_t*)&Ah[m0 * 168 + ac];
            uint32_t aH1 = *(const uint32_t*)&Ah[(m0 + 8) * 168 + ac];
            uint32_t aH2 = *(const uint32_t*)&Ah[m0 * 168 + ac + 8];
            uint32_t aH3 = *(const uint32_t*)&Ah[(m0 + 8) * 168 + ac + 8];
            uint32_t aL0 = *(const uint32_t*)&Al[m0 * 168 + ac];
            uint32_t aL1 = *(const uint32_t*)&Al[(m0 + 8) * 168 + ac];
            uint32_t aL2 = *(const uint32_t*)&Al[m0 * 168 + ac + 8];
            uint32_t aL3 = *(const uint32_t*)&Al[(m0 + 8) * 168 + ac + 8];
#pragma unroll
            for (int nt = 0; nt < 4; nt++) {
                int o = nhalf * 32 + nt * 8 + gid;
                uint32_t bH0 = *(const uint32_t*)&Bh[o * 152 + ac];
                uint32_t bH1 = *(const uint32_t*)&Bh[o * 152 + ac + 8];
                uint32_t bL0 = *(const uint32_t*)&Bl[o * 152 + ac];
                uint32_t bL1 = *(const uint32_t*)&Bl[o * 152 + ac + 8];
                MMA_BF16(acc[nt], aH0, aH1, aH2, aH3, bH0, bH1);
                MMA_BF16(acc[nt], aH0, aH1, aH2, aH3, bL0, bL1);
                MMA_BF16(acc[nt], aL0, aL1, aL2, aL3, bH0, bH1);
            }
        }
#pragma unroll
        for (int nt = 0; nt < 4; nt++) {
            int col = chunk * 64 + nhalf * 32 + nt * 8 + tid4 * 2;
            float2 v01 = {acc[nt][0], acc[nt][1]};
            float2 v23 = {acc[nt][2], acc[nt][3]};
            *(float2*)&dst[(size_t)m0 * 576 + col] = v01;
            *(float2*)&dst[(size_t)(m0 + 8) * 576 + col] = v23;
        }
    }
}

// ============ kernel 3: mamba + residual + wc3 + BN + ReLU (round-14) ============
__global__ void __launch_bounds__(288, 2) k_mamba(
    const float* __restrict__ convd_w, const float* __restrict__ convd_b,
    const float* __restrict__ xproj_w, const float* __restrict__ dtproj_w,
    const float* __restrict__ dtproj_b, const float* __restrict__ A_log,
    const float* __restrict__ Dp, const float* __restrict__ out_w,
    const float* __restrict__ wc3, const float* __restrict__ bc3,
    const float* __restrict__ g3, const float* __restrict__ be3,
    const float* __restrict__ m3, const float* __restrict__ v3,
    float* __restrict__ out)
{
    extern __shared__ float sm[];
    float* uY = sm;
    float* dbl = sm + 18432;
    float* rS = sm + 18432;
    int bi = blockIdx.x, c = threadIdx.x;
    const float* xzb = g_xz + (size_t)bi * 36864;

    {
        const float4* src = (const float4*)xzb;
        float4* dst = (float4*)uY;
        for (int i = c; i < 4608; i += 288) {
            int t = i / 72, ch4 = i - t * 72;
            dst[t * 72 + ch4] = src[t * 144 + ch4];
        }
    }
    __syncthreads();

    {
        float cw0 = convd_w[c * 4], cw1 = convd_w[c * 4 + 1],
              cw2 = convd_w[c * 4 + 2], cw3 = convd_w[c * 4 + 3];
        float cb = convd_b[c];
        float p0 = 0.f, p1 = 0.f, p2 = 0.f;
        for (int t = 0; t < 64; t++) {
            float xt = uY[t * 288 + c];
            float s = cw0 * p0 + cw1 * p1 + cw2 * p2 + cw3 * xt + cb;
            s = s / (1.f + __expf(-s));
            uY[t * 288 + c] = s;
            p0 = p1; p1 = p2; p2 = xt;
        }
    }
    __syncthreads();

    if (c < 164) {
        int j = c % 41, tc = c / 41;
        float acc[16] = {};
        const float4* xw4 = (const float4*)&xproj_w[j * 288];
        const float4* uY4 = (const float4*)uY;
        int tb = tc * 16;
        float4 wv = __ldg(&xw4[0]);
        for (int k4 = 0; k4 < 72; k4++) {
            float4 wn = (k4 < 71) ? __ldg(&xw4[k4 + 1]) : wv;
#pragma unroll
            for (int t = 0; t < 16; t++)
                acc[t] += d4(uY4[(tb + t) * 72 + k4], wv);
            wv = wn;
        }
#pragma unroll
        for (int t = 0; t < 16; t++) dbl[(tb + t) * 48 + j] = acc[t];
    }
    __syncthreads();

    {
        float dtw[9], A[16], h[16];
#pragma unroll
        for (int r = 0; r < 9; r++) dtw[r] = dtproj_w[c * 9 + r];
        float dtb = dtproj_b[c];
#pragma unroll
        for (int n = 0; n < 16; n++) { A[n] = -__expf(A_log[c * 16 + n]); h[n] = 0.f; }
        float dpc = Dp[c];
        for (int t = 0; t < 64; t++) {
            float zv = xzb[t * 576 + 288 + c];
            float dt = dtb;
#pragma unroll
            for (int r = 0; r < 9; r++) dt += dbl[t * 48 + r] * dtw[r];
            float delta = fmaxf(dt, 0.f) + log1pf(__expf(-fabsf(dt)));
            float u = uY[t * 288 + c];
            float dlu = delta * u;
            float y = 0.f;
#pragma unroll
            for (int n = 0; n < 16; n++) {
                float e = __expf(delta * A[n]);
                h[n] = h[n] * e + dlu * dbl[t * 48 + 9 + n];
                y += h[n] * dbl[t * 48 + 25 + n];
            }
            float sz = zv / (1.f + __expf(-zv));
            uY[t * 288 + c] = (y + u * dpc) * sz;
        }
    }
    __syncthreads();

    {
        int o = c % 144, tc = c / 144;
        float acc[32] = {};
        const float4* ow4 = (const float4*)&out_w[o * 288];
        const float4* uY4 = (const float4*)uY;
        int tb = tc * 32;
        float4 wv = __ldg(&ow4[0]);
        for (int k4 = 0; k4 < 72; k4++) {
            float4 wn = (k4 < 71) ? __ldg(&ow4[k4 + 1]) : wv;
#pragma unroll
            for (int t = 0; t < 32; t++)
                acc[t] += d4(uY4[(tb + t) * 72 + k4], wv);
            wv = wn;
        }
        const float* resb = g_h4 + (size_t)bi * 9216;
#pragma unroll
        for (int t = 0; t < 32; t++) {
            int tt = tb + t;
            rS[tt * 144 + o] = acc[t] + __ldg(&resb[tt * 144 + o]);
        }
    }
    __syncthreads();

    for (int i = c; i < 2048; i += 288) {
        int li = i >> 5, oc = i & 31;
        uY[i] = wc3[oc * 64 + li];
    }
    __syncthreads();
    {
        int pt = c % 36, ot = c / 36;
        int p0 = pt * 4, oc0 = ot * 4;
        float a[4][4] = {};
        for (int li = 0; li < 64; li++) {
            float4 w4 = *(const float4*)&uY[li * 32 + oc0];
            float4 x4 = *(const float4*)&rS[li * 144 + p0];
            a[0][0] += w4.x * x4.x; a[0][1] += w4.x * x4.y; a[0][2] += w4.x * x4.z; a[0][3] += w4.x * x4.w;
            a[1][0] += w4.y * x4.x; a[1][1] += w4.y * x4.y; a[1][2] += w4.y * x4.z; a[1][3] += w4.y * x4.w;
            a[2][0] += w4.z * x4.x; a[2][1] += w4.z * x4.y; a[2][2] += w4.z * x4.z; a[2][3] += w4.z * x4.w;
            a[3][0] += w4.w * x4.x; a[3][1] += w4.w * x4.y; a[3][2] += w4.w * x4.z; a[3][3] += w4.w * x4.w;
        }
#pragma unroll
        for (int r = 0; r < 4; r++) {
            int oc = oc0 + r;
            float inv = g3[oc] * rsqrtf(v3[oc] + 1e-5f);
            float sh = (bc3[oc] - m3[oc]) * inv + be3[oc];
            float4 st;
            st.x = fmaxf(a[r][0] * inv + sh, 0.f);
            st.y = fmaxf(a[r][1] * inv + sh, 0.f);
            st.z = fmaxf(a[r][2] * inv + sh, 0.f);
            st.w = fmaxf(a[r][3] * inv + sh, 0.f);
            *(float4*)&out[(size_t)bi * 4608 + oc * 144 + p0] = st;
        }
    }
}

extern "C" void kernel_launch(void* const* d_in, const int* in_sizes, int n_in,
                              void* d_out, int out_size)
{
    const float* x       = (const float*)d_in[0];
    const float* w1      = (const float*)d_in[1];
    const float* b1      = (const float*)d_in[2];
    const float* g1      = (const float*)d_in[3];
    const float* be1     = (const float*)d_in[4];
    const float* m1      = (const float*)d_in[5];
    const float* v1      = (const float*)d_in[6];
    const float* w2      = (const float*)d_in[7];
    const float* b2      = (const float*)d_in[8];
    const float* g2      = (const float*)d_in[9];
    const float* be2     = (const float*)d_in[10];
    const float* m2      = (const float*)d_in[11];
    const float* v2      = (const float*)d_in[12];
    const float* wc2     = (const float*)d_in[13];
    const float* bc2     = (const float*)d_in[14];
    const float* we      = (const float*)d_in[15];
    const float* bee     = (const float*)d_in[16];
    const float* in_w    = (const float*)d_in[17];
    const float* convd_w = (const float*)d_in[18];
    const float* convd_b = (const float*)d_in[19];
    const float* xproj_w = (const float*)d_in[20];
    const float* dtproj_w= (const float*)d_in[21];
    const float* dtproj_b= (const float*)d_in[22];
    const float* A_log   = (const float*)d_in[23];
    const float* Dp      = (const float*)d_in[24];
    const float* out_w   = (const float*)d_in[25];
    const float* wc3     = (const float*)d_in[26];
    const float* bc3     = (const float*)d_in[27];
    const float* g3      = (const float*)d_in[28];
    const float* be3     = (const float*)d_in[29];
    const float* m3      = (const float*)d_in[30];
    const float* v3      = (const float*)d_in[31];

    int B = in_sizes[0] / 28800;

    cudaFuncSetAttribute(k_mid, cudaFuncAttributeMaxDynamicSharedMemorySize, 112640);
    cudaFuncSetAttribute(k_proj, cudaFuncAttributeMaxDynamicSharedMemorySize, 81920);
    cudaFuncSetAttribute(k_mamba, cudaFuncAttributeMaxDynamicSharedMemorySize, 110592);

    k_prep<<<108, 256>>>(in_w);
    k_front<<<B, 288>>>(x, w1, b1, g1, be1, m1, v1);
    k_mid<<<B, 288, 112640>>>(w2, b2, g2, be2, m2, v2, wc2, bc2, we, bee);
    k_proj<<<B, 256, 81920>>>();
    k_mamba<<<B, 288, 110592>>>(convd_w, convd_b, xproj_w, dtproj_w, dtproj_b,
                                A_log, Dp, out_w, wc3, bc3, g3, be3, m3, v3,
                                (float*)d_out);
}

// round 17
// speedup vs baseline: 1.5915x; 1.0591x over previous
#include <cuda_runtime.h>
#include <cuda_bf16.h>
#include <math.h>
#include <stdint.h>
#include <cstdint>

__device__ float g_h1[(size_t)512 * 32 * 144];
__device__ float g_h4[(size_t)512 * 64 * 144];
__device__ float g_xz[(size_t)512 * 64 * 576];
__device__ float g_y[(size_t)512 * 64 * 288];
__device__ __align__(16) __nv_bfloat16 g_bH[576 * 144];
__device__ __align__(16) __nv_bfloat16 g_bL[576 * 144];
__device__ __align__(16) __nv_bfloat16 g_oH[144 * 288];
__device__ __align__(16) __nv_bfloat16 g_oL[144 * 288];

__device__ __forceinline__ float d4(float4 a, float4 b) {
    return a.x * b.x + a.y * b.y + a.z * b.z + a.w * b.w;
}

#define MMA_BF16(acc, a0, a1, a2, a3, b0, b1) \
    asm volatile("mma.sync.aligned.m16n8k16.row.col.f32.bf16.bf16.f32 " \
                 "{%0,%1,%2,%3}, {%4,%5,%6,%7}, {%8,%9}, {%0,%1,%2,%3};" \
                 : "+f"((acc)[0]), "+f"((acc)[1]), "+f"((acc)[2]), "+f"((acc)[3]) \
                 : "r"(a0), "r"(a1), "r"(a2), "r"(a3), "r"(b0), "r"(b1))

// ============ kernel 0: split in_w and out_w into bf16 hi/lo ============
__global__ void k_prep(const float* __restrict__ in_w, const float* __restrict__ out_w) {
    int i = blockIdx.x * blockDim.x + threadIdx.x;
    for (; i < 576 * 144; i += gridDim.x * blockDim.x) {
        float v = in_w[i];
        __nv_bfloat16 hi = __float2bfloat16(v);
        g_bH[i] = hi;
        g_bL[i] = __float2bfloat16(v - __bfloat162float(hi));
        if (i < 144 * 288) {
            float w = out_w[i];
            __nv_bfloat16 whi = __float2bfloat16(w);
            g_oH[i] = whi;
            g_oL[i] = __float2bfloat16(w - __bfloat162float(whi));
        }
    }
}

// ============ kernel 1: conv1(200->32,3x3,pad1)+BN+ReLU via mma.sync (round-16) ============
__global__ void __launch_bounds__(288, 3) k_front(
    const float* __restrict__ x, const float* __restrict__ w1,
    const float* __restrict__ b1, const float* __restrict__ g1,
    const float* __restrict__ be1, const float* __restrict__ m1,
    const float* __restrict__ v1)
{
    __shared__ __nv_bfloat16 iTh[196 * 16], iTl[196 * 16];
    __shared__ __nv_bfloat16 wTh[9 * 32 * 16], wTl[9 * 32 * 16];
    int tid = threadIdx.x, wid = tid >> 5, lane = tid & 31;
    int gid = lane >> 2, tid4 = lane & 3;
    size_t bi = blockIdx.x;
    const float* xb = x + bi * 28800;

    for (int i = tid; i < 196 * 16; i += 288) { iTh[i] = __float2bfloat16(0.f); iTl[i] = __float2bfloat16(0.f); }

    int r0 = wid * 16 + gid, r1 = r0 + 8;
    int y0 = r0 / 12, x0 = r0 - y0 * 12;
    int y1 = r1 / 12, x1 = r1 - y1 * 12;
    float acc[4][4] = {};

    for (int chunk = 0; chunk < 13; chunk++) {
        __syncthreads();
        for (int i = tid; i < 2304; i += 288) {
            int ici = i / 144, pos = i - ici * 144;
            int ic = chunk * 16 + ici;
            float v = (ic < 200) ? xb[ic * 144 + pos] : 0.f;
            int yy = pos / 12, xx = pos - yy * 12;
            int idx = ((yy + 1) * 14 + xx + 1) * 16 + ici;
            __nv_bfloat16 hi = __float2bfloat16(v);
            iTh[idx] = hi;
            iTl[idx] = __float2bfloat16(v - __bfloat162float(hi));
        }
        for (int i = tid; i < 4608; i += 288) {
            int tap = i >> 9, rem = i & 511;
            int oc = rem >> 4, ici = rem & 15;
            int ic = chunk * 16 + ici;
            float v = (ic < 200) ? w1[oc * 1800 + ic * 9 + tap] : 0.f;
            __nv_bfloat16 hi = __float2bfloat16(v);
            wTh[i] = hi;
            wTl[i] = __float2bfloat16(v - __bfloat162float(hi));
        }
        __syncthreads();
#pragma unroll 1
        for (int tap = 0; tap < 9; tap++) {
            int dy = tap / 3, dx = tap - dy * 3;
            int p0 = ((y0 + dy) * 14 + x0 + dx) * 16 + tid4 * 2;
            int p1 = ((y1 + dy) * 14 + x1 + dx) * 16 + tid4 * 2;
            uint32_t aH0 = *(const uint32_t*)&iTh[p0];
            uint32_t aH1 = *(const uint32_t*)&iTh[p1];
            uint32_t aH2 = *(const uint32_t*)&iTh[p0 + 8];
            uint32_t aH3 = *(const uint32_t*)&iTh[p1 + 8];
            uint32_t aL0 = *(const uint32_t*)&iTl[p0];
            uint32_t aL1 = *(const uint32_t*)&iTl[p1];
            uint32_t aL2 = *(const uint32_t*)&iTl[p0 + 8];
            uint32_t aL3 = *(const uint32_t*)&iTl[p1 + 8];
#pragma unroll
            for (int nt = 0; nt < 4; nt++) {
                int wb = (tap * 32 + nt * 8 + gid) * 16 + tid4 * 2;
                uint32_t bH0 = *(const uint32_t*)&wTh[wb];
                uint32_t bH1 = *(const uint32_t*)&wTh[wb + 8];
                uint32_t bL0 = *(const uint32_t*)&wTl[wb];
                uint32_t bL1 = *(const uint32_t*)&wTl[wb + 8];
                MMA_BF16(acc[nt], aH0, aH1, aH2, aH3, bH0, bH1);
                MMA_BF16(acc[nt], aH0, aH1, aH2, aH3, bL0, bL1);
                MMA_BF16(acc[nt], aL0, aL1, aL2, aL3, bH0, bH1);
            }
        }
    }
#pragma unroll
    for (int nt = 0; nt < 4; nt++) {
        int oc0 = nt * 8 + tid4 * 2;
#pragma unroll
        for (int cc = 0; cc < 2; cc++) {
            int oc = oc0 + cc;
            float inv = g1[oc] * rsqrtf(v1[oc] + 1e-5f);
            float sh = (b1[oc] - m1[oc]) * inv + be1[oc];
            g_h1[bi * 4608 + oc * 144 + r0] = fmaxf(acc[nt][cc] * inv + sh, 0.f);
            g_h1[bi * 4608 + oc * 144 + r1] = fmaxf(acc[nt][2 + cc] * inv + sh, 0.f);
        }
    }
}

// ============ kernel 2: conv2+BN+ReLU -> we -> wc2 (round-14) ============
__global__ void __launch_bounds__(288, 2) k_mid(
    const float* __restrict__ w2, const float* __restrict__ b2,
    const float* __restrict__ g2, const float* __restrict__ be2,
    const float* __restrict__ m2, const float* __restrict__ v2,
    const float* __restrict__ wc2, const float* __restrict__ bc2,
    const float* __restrict__ we, const float* __restrict__ bee)
{
    extern __shared__ float sm[];
    float* ws2 = sm;
    float* img = sm + 4608;
    float* stage = sm;
    float* h3 = sm + 9216;
    float* h2 = sm + 18688;
    int bi = blockIdx.x, tid = threadIdx.x;

    for (int i = tid; i < 6272; i += 288) img[i] = 0.f;
    __syncthreads();
    for (int i = tid; i < 4608; i += 288) {
        int ic = i / 144, pos = i - ic * 144;
        int y = pos / 12, xx = pos - y * 12;
        img[ic * 196 + (y + 1) * 14 + xx + 1] = g_h1[(size_t)bi * 4608 + i];
    }
    {
        int pg = tid % 18, ocg = tid / 18;
        int ry = (pg / 3) * 2, cx = (pg % 3) * 4;
        float acc[2][4][4] = {};
        for (int c0 = 0; c0 < 32; c0 += 8) {
            __syncthreads();
            for (int i = tid; i < 4608; i += 288) {
                int ic = i / 576, rr = i - ic * 576;
                ws2[i] = w2[(rr & 63) * 288 + (c0 + ic) * 9 + (rr >> 6)];
            }
            __syncthreads();
#pragma unroll 1
            for (int ic = 0; ic < 8; ic++) {
                float xv[4][6];
                const float* xp = &img[(c0 + ic) * 196 + ry * 14 + cx];
#pragma unroll
                for (int rr = 0; rr < 4; rr++)
#pragma unroll
                    for (int cc = 0; cc < 6; cc++) xv[rr][cc] = xp[rr * 14 + cc];
#pragma unroll
                for (int k = 0; k < 9; k++) {
                    float4 wv = *(const float4*)&ws2[ic * 576 + k * 64 + ocg * 4];
                    int kr = k / 3, kc = k % 3;
#pragma unroll
                    for (int orow = 0; orow < 2; orow++)
#pragma unroll
                        for (int q = 0; q < 4; q++) {
                            float xvv = xv[orow + kr][kc + q];
                            acc[orow][0][q] += wv.x * xvv;
                            acc[orow][1][q] += wv.y * xvv;
                            acc[orow][2][q] += wv.z * xvv;
                            acc[orow][3][q] += wv.w * xvv;
                        }
                }
            }
        }
        __syncthreads();
#pragma unroll
        for (int o = 0; o < 4; o++) {
            int oc = (tid / 18) * 4 + o;
            float inv = g2[oc] * rsqrtf(v2[oc] + 1e-5f);
            float sh = (b2[oc] - m2[oc]) * inv + be2[oc];
#pragma unroll
            for (int orow = 0; orow < 2; orow++)
#pragma unroll
                for (int q = 0; q < 4; q++)
                    h2[oc * 148 + (ry + orow) * 12 + cx + q] =
                        fmaxf(acc[orow][o][q] * inv + sh, 0.f);
        }
    }

    // phase B: h3 = h2 @ we^T + bee
    {
        int oslot = tid % 48, tc = tid / 48;
        const float4* h24 = (const float4*)h2;
        for (int o0 = 0; o0 < 144; o0 += 48) {
            __syncthreads();
            for (int i = tid; i < 48 * 144; i += 288) {
                int o = i / 144, k = i - o * 144;
                stage[o * 148 + k] = we[(o0 + o) * 144 + k];
            }
            __syncthreads();
            if (tid < 192) {
                float acc[16] = {};
                const float4* w4 = (const float4*)&stage[oslot * 148];
                int tb = tc * 16;
                for (int k4 = 0; k4 < 36; k4++) {
                    float4 wv = w4[k4];
#pragma unroll
                    for (int t = 0; t < 16; t++)
                        acc[t] += d4(h24[(tb + t) * 37 + k4], wv);
                }
                float bb = bee[o0 + oslot];
#pragma unroll
                for (int t = 0; t < 16; t++)
                    h3[(tb + t) * 148 + o0 + oslot] = acc[t] + bb;
            }
        }
    }

    // phase C: h4 = wc2-mix(h3)+bc2 -> g_h4
    __syncthreads();
    for (int i = tid; i < 4096; i += 288) {
        int li = i >> 6, lo = i & 63;
        stage[i] = wc2[lo * 64 + li];
    }
    __syncthreads();
    for (int tt = tid; tt < 576; tt += 288) {
        int pt = tt % 36, lt = tt / 36;
        int p0 = pt * 4, lo0 = lt * 4;
        float a[4][4] = {};
        for (int li = 0; li < 64; li++) {
            float4 w4 = *(const float4*)&stage[li * 64 + lo0];
            float4 x4 = *(const float4*)&h3[li * 148 + p0];
            a[0][0] += w4.x * x4.x; a[0][1] += w4.x * x4.y; a[0][2] += w4.x * x4.z; a[0][3] += w4.x * x4.w;
            a[1][0] += w4.y * x4.x; a[1][1] += w4.y * x4.y; a[1][2] += w4.y * x4.z; a[1][3] += w4.y * x4.w;
            a[2][0] += w4.z * x4.x; a[2][1] += w4.z * x4.y; a[2][2] += w4.z * x4.z; a[2][3] += w4.z * x4.w;
            a[3][0] += w4.w * x4.x; a[3][1] += w4.w * x4.y; a[3][2] += w4.w * x4.z; a[3][3] += w4.w * x4.w;
        }
#pragma unroll
        for (int r = 0; r < 4; r++) {
            float bb = bc2[lo0 + r];
            float4 st = {a[r][0] + bb, a[r][1] + bb, a[r][2] + bb, a[r][3] + bb};
            *(float4*)&g_h4[(size_t)bi * 9216 + (lo0 + r) * 144 + p0] = st;
        }
    }
}

// ============ kernel 2.5: xz = h4 @ in_w^T via mma.sync (round-14) ============
__global__ void __launch_bounds__(256, 2) k_proj() {
    extern __shared__ unsigned char smp[];
    __nv_bfloat16* Ah = (__nv_bfloat16*)smp;
    __nv_bfloat16* Al = (__nv_bfloat16*)(smp + 21504);
    __nv_bfloat16* Bh = (__nv_bfloat16*)(smp + 43008);
    __nv_bfloat16* Bl = (__nv_bfloat16*)(smp + 62464);
    int tid = threadIdx.x, wid = tid >> 5, lane = tid & 31;
    int gid = lane >> 2, tid4 = lane & 3;
    size_t bi = blockIdx.x;
    const float* h4 = g_h4 + bi * 9216;

    for (int i = tid; i < 9216; i += 256) {
        int r = i / 144, c = i - r * 144;
        float v = h4[i];
        __nv_bfloat16 hi = __float2bfloat16(v);
        Ah[r * 168 + c] = hi;
        Al[r * 168 + c] = __float2bfloat16(v - __bfloat162float(hi));
    }

    int mtile = wid >> 1, nhalf = wid & 1;
    int m0 = mtile * 16 + gid;
    float* dst = g_xz + bi * 36864;

    for (int chunk = 0; chunk < 9; chunk++) {
        __syncthreads();
        {
            const uint4* sH = (const uint4*)(g_bH + chunk * 64 * 144);
            const uint4* sL = (const uint4*)(g_bL + chunk * 64 * 144);
            for (int i = tid; i < 1152; i += 256) {
                int row = i / 18, w = i - row * 18;
                ((uint4*)Bh)[row * 19 + w] = sH[i];
                ((uint4*)Bl)[row * 19 + w] = sL[i];
            }
        }
        __syncthreads();

        float acc[4][4] = {};
#pragma unroll 1
        for (int k = 0; k < 9; k++) {
            int ac = k * 16 + tid4 * 2;
            uint32_t aH0 = *(const uint32_t*)&Ah[m0 * 168 + ac];
            uint32_t aH1 = *(const uint32_t*)&Ah[(m0 + 8) * 168 + ac];
            uint32_t aH2 = *(const uint32_t*)&Ah[m0 * 168 + ac + 8];
            uint32_t aH3 = *(const uint32_t*)&Ah[(m0 + 8) * 168 + ac + 8];
            uint32_t aL0 = *(const uint32_t*)&Al[m0 * 168 + ac];
            uint32_t aL1 = *(const uint32_t*)&Al[(m0 + 8) * 168 + ac];
            uint32_t aL2 = *(const uint32_t*)&Al[m0 * 168 + ac + 8];
            uint32_t aL3 = *(const uint32_t*)&Al[(m0 + 8) * 168 + ac + 8];
#pragma unroll
            for (int nt = 0; nt < 4; nt++) {
                int o = nhalf * 32 + nt * 8 + gid;
                uint32_t bH0 = *(const uint32_t*)&Bh[o * 152 + ac];
                uint32_t bH1 = *(const uint32_t*)&Bh[o * 152 + ac + 8];
                uint32_t bL0 = *(const uint32_t*)&Bl[o * 152 + ac];
                uint32_t bL1 = *(const uint32_t*)&Bl[o * 152 + ac + 8];
                MMA_BF16(acc[nt], aH0, aH1, aH2, aH3, bH0, bH1);
                MMA_BF16(acc[nt], aH0, aH1, aH2, aH3, bL0, bL1);
                MMA_BF16(acc[nt], aL0, aL1, aL2, aL3, bH0, bH1);
            }
        }
#pragma unroll
        for (int nt = 0; nt < 4; nt++) {
            int col = chunk * 64 + nhalf * 32 + nt * 8 + tid4 * 2;
            float2 v01 = {acc[nt][0], acc[nt][1]};
            float2 v23 = {acc[nt][2], acc[nt][3]};
            *(float2*)&dst[(size_t)m0 * 576 + col] = v01;
            *(float2*)&dst[(size_t)(m0 + 8) * 576 + col] = v23;
        }
    }
}

// ============ kernel 3: mamba (ends after gate; y -> g_y) ============
__global__ void __launch_bounds__(288, 2) k_mamba(
    const float* __restrict__ convd_w, const float* __restrict__ convd_b,
    const float* __restrict__ xproj_w, const float* __restrict__ dtproj_w,
    const float* __restrict__ dtproj_b, const float* __restrict__ A_log,
    const float* __restrict__ Dp)
{
    extern __shared__ float sm[];
    float* uY = sm;                  // 18432
    float* dbl = sm + 18432;         // 3072
    int bi = blockIdx.x, c = threadIdx.x;
    const float* xzb = g_xz + (size_t)bi * 36864;

    {
        const float4* src = (const float4*)xzb;
        float4* dst = (float4*)uY;
        for (int i = c; i < 4608; i += 288) {
            int t = i / 72, ch4 = i - t * 72;
            dst[t * 72 + ch4] = src[t * 144 + ch4];
        }
    }
    __syncthreads();

    {
        float cw0 = convd_w[c * 4], cw1 = convd_w[c * 4 + 1],
              cw2 = convd_w[c * 4 + 2], cw3 = convd_w[c * 4 + 3];
        float cb = convd_b[c];
        float p0 = 0.f, p1 = 0.f, p2 = 0.f;
        for (int t = 0; t < 64; t++) {
            float xt = uY[t * 288 + c];
            float s = cw0 * p0 + cw1 * p1 + cw2 * p2 + cw3 * xt + cb;
            s = s / (1.f + __expf(-s));
            uY[t * 288 + c] = s;
            p0 = p1; p1 = p2; p2 = xt;
        }
    }
    __syncthreads();

    if (c < 164) {
        int j = c % 41, tc = c / 41;
        float acc[16] = {};
        const float4* xw4 = (const float4*)&xproj_w[j * 288];
        const float4* uY4 = (const float4*)uY;
        int tb = tc * 16;
        float4 wv = __ldg(&xw4[0]);
        for (int k4 = 0; k4 < 72; k4++) {
            float4 wn = (k4 < 71) ? __ldg(&xw4[k4 + 1]) : wv;
#pragma unroll
            for (int t = 0; t < 16; t++)
                acc[t] += d4(uY4[(tb + t) * 72 + k4], wv);
            wv = wn;
        }
#pragma unroll
        for (int t = 0; t < 16; t++) dbl[(tb + t) * 48 + j] = acc[t];
    }
    __syncthreads();

    {
        float dtw[9], A[16], h[16];
#pragma unroll
        for (int r = 0; r < 9; r++) dtw[r] = dtproj_w[c * 9 + r];
        float dtb = dtproj_b[c];
#pragma unroll
        for (int n = 0; n < 16; n++) { A[n] = -__expf(A_log[c * 16 + n]); h[n] = 0.f; }
        float dpc = Dp[c];
        float* yb = g_y + (size_t)bi * 18432;
        for (int t = 0; t < 64; t++) {
            float zv = xzb[t * 576 + 288 + c];
            float dt = dtb;
#pragma unroll
            for (int r = 0; r < 9; r++) dt += dbl[t * 48 + r] * dtw[r];
            float delta = fmaxf(dt, 0.f) + log1pf(__expf(-fabsf(dt)));
            float u = uY[t * 288 + c];
            float dlu = delta * u;
            float y = 0.f;
#pragma unroll
            for (int n = 0; n < 16; n++) {
                float e = __expf(delta * A[n]);
                h[n] = h[n] * e + dlu * dbl[t * 48 + 9 + n];
                y += h[n] * dbl[t * 48 + 25 + n];
            }
            float sz = zv / (1.f + __expf(-zv));
            yb[t * 288 + c] = (y + u * dpc) * sz;
        }
    }
}

// ============ kernel 3.5: out-proj (MMA) + residual + wc3 + BN + ReLU ============
// 256 thr / 8 warps; warp = (mtile 0..3, nhalf 0..1 covering 72 cols each).
// SMEM: Ah[64][296] @0 (37888 B), Al @37888; later rS[64][152] fl overlays @0,
// wc3T (2048 fl) @38912. Total 75776 B -> 2 CTA/SM.
__global__ void __launch_bounds__(256, 2) k_oproj(
    const float* __restrict__ wc3, const float* __restrict__ bc3,
    const float* __restrict__ g3, const float* __restrict__ be3,
    const float* __restrict__ m3, const float* __restrict__ v3,
    float* __restrict__ out)
{
    extern __shared__ unsigned char smp[];
    __nv_bfloat16* Ah = (__nv_bfloat16*)smp;
    __nv_bfloat16* Al = (__nv_bfloat16*)(smp + 37888);
    float* rSf = (float*)smp;                 // stride 152, after MMA
    float* wc3T = (float*)(smp + 38912);      // 2048 fl
    int tid = threadIdx.x, wid = tid >> 5, lane = tid & 31;
    int gid = lane >> 2, tid4 = lane & 3;
    size_t bi = blockIdx.x;
    const float* yb = g_y + bi * 18432;

    for (int i = tid; i < 18432; i += 256) {
        int r = i / 288, c = i - r * 288;
        float v = yb[i];
        __nv_bfloat16 hi = __float2bfloat16(v);
        Ah[r * 296 + c] = hi;
        Al[r * 296 + c] = __float2bfloat16(v - __bfloat162float(hi));
    }
    __syncthreads();

    int mtile = wid >> 1, nhalf = wid & 1;
    int m0 = mtile * 16 + gid, m1 = m0 + 8;
    float acc[9][4] = {};
#pragma unroll 1
    for (int k = 0; k < 18; k++) {
        int ac = k * 16 + tid4 * 2;
        uint32_t aH0 = *(const uint32_t*)&Ah[m0 * 296 + ac];
        uint32_t aH1 = *(const uint32_t*)&Ah[m1 * 296 + ac];
        uint32_t aH2 = *(const uint32_t*)&Ah[m0 * 296 + ac + 8];
        uint32_t aH3 = *(const uint32_t*)&Ah[m1 * 296 + ac + 8];
        uint32_t aL0 = *(const uint32_t*)&Al[m0 * 296 + ac];
        uint32_t aL1 = *(const uint32_t*)&Al[m1 * 296 + ac];
        uint32_t aL2 = *(const uint32_t*)&Al[m0 * 296 + ac + 8];
        uint32_t aL3 = *(const uint32_t*)&Al[m1 * 296 + ac + 8];
#pragma unroll
        for (int nt = 0; nt < 9; nt++) {
            int o = nhalf * 72 + nt * 8 + gid;
            uint32_t bH0 = __ldg((const uint32_t*)&g_oH[o * 288 + ac]);
            uint32_t bH1 = __ldg((const uint32_t*)&g_oH[o * 288 + ac + 8]);
            uint32_t bL0 = __ldg((const uint32_t*)&g_oL[o * 288 + ac]);
            uint32_t bL1 = __ldg((const uint32_t*)&g_oL[o * 288 + ac + 8]);
            MMA_BF16(acc[nt], aH0, aH1, aH2, aH3, bH0, bH1);
            MMA_BF16(acc[nt], aH0, aH1, aH2, aH3, bL0, bL1);
            MMA_BF16(acc[nt], aL0, aL1, aL2, aL3, bH0, bH1);
        }
    }
    __syncthreads();   // all Ah/Al reads done; safe to overlay rS

    // rS = out-proj + residual
    {
        const float* resb = g_h4 + bi * 9216;
#pragma unroll
        for (int nt = 0; nt < 9; nt++) {
            int c0 = nhalf * 72 + nt * 8 + tid4 * 2;
            float2 r01 = *(const float2*)&resb[m0 * 144 + c0];
            float2 r23 = *(const float2*)&resb[m1 * 144 + c0];
            float2 v01 = {acc[nt][0] + r01.x, acc[nt][1] + r01.y};
            float2 v23 = {acc[nt][2] + r23.x, acc[nt][3] + r23.y};
            *(float2*)&rSf[m0 * 152 + c0] = v01;
            *(float2*)&rSf[m1 * 152 + c0] = v23;
        }
    }
    for (int i = tid; i < 2048; i += 256) {
        int li = i >> 5, oc = i & 31;
        wc3T[li * 32 + oc] = wc3[oc * 64 + li];
    }
    __syncthreads();

    // wc3 (64->32 token mix) + BN + ReLU -> out, 4x4 tiles
    for (int tt = tid; tt < 288; tt += 256) {
        int pt = tt % 36, ot = tt / 36;
        int p0 = pt * 4, oc0 = ot * 4;
        float a[4][4] = {};
        for (int li = 0; li < 64; li++) {
            float4 w4 = *(const float4*)&wc3T[li * 32 + oc0];
            float4 x4 = *(const float4*)&rSf[li * 152 + p0];
            a[0][0] += w4.x * x4.x; a[0][1] += w4.x * x4.y; a[0][2] += w4.x * x4.z; a[0][3] += w4.x * x4.w;
            a[1][0] += w4.y * x4.x; a[1][1] += w4.y * x4.y; a[1][2] += w4.y * x4.z; a[1][3] += w4.y * x4.w;
            a[2][0] += w4.z * x4.x; a[2][1] += w4.z * x4.y; a[2][2] += w4.z * x4.z; a[2][3] += w4.z * x4.w;
            a[3][0] += w4.w * x4.x; a[3][1] += w4.w * x4.y; a[3][2] += w4.w * x4.z; a[3][3] += w4.w * x4.w;
        }
#pragma unroll
        for (int r = 0; r < 4; r++) {
            int oc = oc0 + r;
            float inv = g3[oc] * rsqrtf(v3[oc] + 1e-5f);
            float sh = (bc3[oc] - m3[oc]) * inv + be3[oc];
            float4 st;
            st.x = fmaxf(a[r][0] * inv + sh, 0.f);
            st.y = fmaxf(a[r][1] * inv + sh, 0.f);
            st.z = fmaxf(a[r][2] * inv + sh, 0.f);
            st.w = fmaxf(a[r][3] * inv + sh, 0.f);
            *(float4*)&out[bi * 4608 + oc * 144 + p0] = st;
        }
    }
}

extern "C" void kernel_launch(void* const* d_in, const int* in_sizes, int n_in,
                              void* d_out, int out_size)
{
    const float* x       = (const float*)d_in[0];
    const float* w1      = (const float*)d_in[1];
    const float* b1      = (const float*)d_in[2];
    const float* g1      = (const float*)d_in[3];
    const float* be1     = (const float*)d_in[4];
    const float* m1      = (const float*)d_in[5];
    const float* v1      = (const float*)d_in[6];
    const float* w2      = (const float*)d_in[7];
    const float* b2      = (const float*)d_in[8];
    const float* g2      = (const float*)d_in[9];
    const float* be2     = (const float*)d_in[10];
    const float* m2      = (const float*)d_in[11];
    const float* v2      = (const float*)d_in[12];
    const float* wc2     = (const float*)d_in[13];
    const float* bc2     = (const float*)d_in[14];
    const float* we      = (const float*)d_in[15];
    const float* bee     = (const float*)d_in[16];
    const float* in_w    = (const float*)d_in[17];
    const float* convd_w = (const float*)d_in[18];
    const float* convd_b = (const float*)d_in[19];
    const float* xproj_w = (const float*)d_in[20];
    const float* dtproj_w= (const float*)d_in[21];
    const float* dtproj_b= (const float*)d_in[22];
    const float* A_log   = (const float*)d_in[23];
    const float* Dp      = (const float*)d_in[24];
    const float* out_w   = (const float*)d_in[25];
    const float* wc3     = (const float*)d_in[26];
    const float* bc3     = (const float*)d_in[27];
    const float* g3      = (const float*)d_in[28];
    const float* be3     = (const float*)d_in[29];
    const float* m3      = (const float*)d_in[30];
    const float* v3      = (const float*)d_in[31];

    int B = in_sizes[0] / 28800;

    cudaFuncSetAttribute(k_mid, cudaFuncAttributeMaxDynamicSharedMemorySize, 112640);
    cudaFuncSetAttribute(k_proj, cudaFuncAttributeMaxDynamicSharedMemorySize, 81920);
    cudaFuncSetAttribute(k_mamba, cudaFuncAttributeMaxDynamicSharedMemorySize, 86016);
    cudaFuncSetAttribute(k_oproj, cudaFuncAttributeMaxDynamicSharedMemorySize, 75776);

    k_prep<<<108, 256>>>(in_w, out_w);
    k_front<<<B, 288>>>(x, w1, b1, g1, be1, m1, v1);
    k_mid<<<B, 288, 112640>>>(w2, b2, g2, be2, m2, v2, wc2, bc2, we, bee);
    k_proj<<<B, 256, 81920>>>();
    k_mamba<<<B, 288, 86016>>>(convd_w, convd_b, xproj_w, dtproj_w, dtproj_b,
                               A_log, Dp);
    k_oproj<<<B, 256, 75776>>>(wc3, bc3, g3, be3, m3, v3, (float*)d_out);
}